// round 8
// baseline (speedup 1.0000x reference)
#include <cuda_runtime.h>
#include <cuda_fp16.h>
#include <cstdint>

#define B_DIM 16
#define C_DIM 64
#define K_DIM 207
#define L_DIM 64
#define KL 13248          // K_DIM * L_DIM
#define CKL (C_DIM * KL)  // 847872
#define KK2 42849         // K_DIM * K_DIM
#define CLDIM 4096        // C_DIM * L_DIM
#define KP 256            // padded K / M for tensor path
#define CIN 320           // conv input channels
#define NH 13312          // padded (j,l) rows = 52*256

// Does this device-compilation pass support tcgen05? ('a'-arch targets only)
#if defined(__CUDA_ARCH_FEAT_SM103_ALL) || defined(__CUDA_ARCH_FEAT_SM100_ALL) || \
    defined(__CUDA_ARCH_FEAT_SM101_ALL)
#define HAVE_TC 1
#else
#define HAVE_TC 0
#endif

// Scratch (device globals: allocation-free per harness rules; zero-initialized)
__device__ __half g_Ah[B_DIM][4][KP][KP];             // A hi; s:0=A0,1=A0^2,2=A1,3=A1^2
__device__ __half g_Al[B_DIM][4][KP][KP];             // A lo
__device__ __half g_ATh[B_DIM][2][KP][KP];            // A^T hi (for squaring), s2:0=A0,1=A1
__device__ __half g_ATl[B_DIM][2][KP][KP];            // A^T lo
__device__ __half g_Xh[B_DIM][CLDIM][KP];             // X^T hi: [b][l*64+c][k]
__device__ __half g_Xl[B_DIM][CLDIM][KP];             // X^T lo
__device__ __half g_hh[B_DIM][NH][CIN];               // h=[x;G] hi: [b][j*64+l][ch]
__device__ __half g_hl[B_DIM][NH][CIN];               // h lo
__device__ __half g_Wh[128][CIN];                     // W hi, rows 64..127 zero
__device__ __half g_Wl[128][CIN];                     // W lo

// ---------- packed f32x2 helpers ----------
__device__ __forceinline__ unsigned long long pack2(float lo, float hi) {
    unsigned long long r;
    asm("mov.b64 %0, {%1, %2};" : "=l"(r) : "f"(lo), "f"(hi));
    return r;
}
__device__ __forceinline__ void fma2(unsigned long long& d, unsigned long long a,
                                     unsigned long long b) {
    asm("fma.rn.f32x2 %0, %1, %2, %0;" : "+l"(d) : "l"(a), "l"(b));
}
__device__ __forceinline__ float2 unpack2(unsigned long long v) {
    float2 f;
    asm("mov.b64 {%0, %1}, %2;" : "=f"(f.x), "=f"(f.y) : "l"(v));
    return f;
}
__device__ __forceinline__ void split_hl(float v, __half& hi, __half& lo) {
    hi = __float2half_rn(v);
    lo = __float2half_rn(v - __half2float(hi));
}

// ---------- FFMA 64x64 microkernel (fallback paths only) ----------
__device__ __forceinline__ void mm_tile(const float* __restrict__ As,
                                        const float* __restrict__ Bs,
                                        unsigned long long (&acc)[4][2],
                                        int ty, int tx) {
#pragma unroll
    for (int kk = 0; kk < 16; ++kk) {
        float4 av = *(const float4*)(As + kk * 68 + ty * 4);
        float4 bv = *(const float4*)(Bs + kk * 64 + tx * 4);
        unsigned long long b01 = pack2(bv.x, bv.y);
        unsigned long long b23 = pack2(bv.z, bv.w);
        unsigned long long a;
        a = pack2(av.x, av.x); fma2(acc[0][0], a, b01); fma2(acc[0][1], a, b23);
        a = pack2(av.y, av.y); fma2(acc[1][0], a, b01); fma2(acc[1][1], a, b23);
        a = pack2(av.z, av.z); fma2(acc[2][0], a, b01); fma2(acc[2][1], a, b23);
        a = pack2(av.w, av.w); fma2(acc[3][0], a, b01); fma2(acc[3][1], a, b23);
    }
}

// ---------- prep: A (s=0,2) -> fp16 hi/lo, zero-padded; grid (256, 32) ----------
__global__ __launch_bounds__(256) void prep_A(const float* __restrict__ a0,
                                              const float* __restrict__ a1) {
    int j = blockIdx.x;            // 0..255
    int bz = blockIdx.y;           // b*2+s2
    int b = bz >> 1, s2 = bz & 1;
    int k = threadIdx.x;
    const float* src = (s2 ? a1 : a0) + b * KK2;
    float v = (j < K_DIM && k < K_DIM) ? src[j * K_DIM + k] : 0.f;
    __half hi, lo;
    split_hl(v, hi, lo);
    g_Ah[b][2 * s2][j][k] = hi;
    g_Al[b][2 * s2][j][k] = lo;
}

// ---------- prep: A^T (s2=0,1) via smem transpose; grid (4, 4, 32) ----------
__global__ __launch_bounds__(256) void prep_AT(const float* __restrict__ a0,
                                               const float* __restrict__ a1) {
    __shared__ float s[64][65];
    int kt = blockIdx.x, jt = blockIdx.y, bz = blockIdx.z;
    int b = bz >> 1, s2 = bz & 1;
    const float* src = (s2 ? a1 : a0) + b * KK2;
    int t = threadIdx.x;
    int col = t & 63, row4 = t >> 6;
#pragma unroll
    for (int it = 0; it < 16; ++it) {
        int lj = it * 4 + row4;
        int j = jt * 64 + lj, k = kt * 64 + col;
        s[lj][col] = (j < K_DIM && k < K_DIM) ? src[j * K_DIM + k] : 0.f;
    }
    __syncthreads();
#pragma unroll
    for (int it = 0; it < 16; ++it) {
        int r = it * 4 + row4;          // local k
        float v = s[col][r];            // AT[k][j] = A[j][k]
        __half hi, lo;
        split_hl(v, hi, lo);
        g_ATh[b][s2][kt * 64 + r][jt * 64 + col] = hi;
        g_ATl[b][s2][kt * 64 + r][jt * 64 + col] = lo;
    }
}

// ---------- prep: transpose X to [b][l*64+c][k] fp16 hi/lo; 512 thr, float4 ----
__global__ __launch_bounds__(512) void prep_X(const float* __restrict__ x) {
    extern __shared__ float s_x[];     // [207][68]
    int c = blockIdx.x, b = blockIdx.y;
    const float* xp = x + (long)b * CKL + (long)c * KL;
    int t = threadIdx.x;
    // 13248 floats = 3312 float4; layout [k][l], row pad 68 (272B, 16B-aligned)
#pragma unroll
    for (int it = 0; it < 7; ++it) {
        int idx = it * 512 + t;
        if (idx < 3312) {
            float4 v = ((const float4*)xp)[idx];
            int k = idx >> 4, l4 = (idx & 15) * 4;
            *(float4*)&s_x[k * 68 + l4] = v;
        }
    }
    __syncthreads();
    int kq = t >> 6, l = t & 63;       // kq 0..7, each handles 32 k
    __align__(16) __half hh[32], hl[32];
#pragma unroll
    for (int i = 0; i < 32; ++i) {
        int k = kq * 32 + i;
        float v = (k < K_DIM) ? s_x[k * 68 + l] : 0.f;
        split_hl(v, hh[i], hl[i]);
    }
    uint4* dh = (uint4*)&g_Xh[b][l * 64 + c][kq * 32];
    uint4* dl = (uint4*)&g_Xl[b][l * 64 + c][kq * 32];
#pragma unroll
    for (int i = 0; i < 4; ++i) { dh[i] = ((uint4*)hh)[i]; dl[i] = ((uint4*)hl)[i]; }
}

// ---------- prep: x -> channels [0,64) of g_h (hi/lo), grid (207, 16) ----------
__global__ __launch_bounds__(256) void prep_xh(const float* __restrict__ x) {
    __shared__ float sx[64][68];
    int j = blockIdx.x, b = blockIdx.y;
    int t = threadIdx.x;
    const float* xp = x + (long)b * CKL + j * 64;
    // 64 channels x 64 l = 1024 float4 rows? -> 64*64 floats = 1024 float4
#pragma unroll
    for (int it = 0; it < 4; ++it) {
        int idx = it * 256 + t;        // float4 index within [c][l]
        int c = idx >> 4, l4 = (idx & 15) * 4;
        float4 v = *(const float4*)(xp + (long)c * KL + l4);
        *(float4*)&sx[c][l4] = v;
    }
    __syncthreads();
#pragma unroll
    for (int it = 0; it < 2; ++it) {
        int idx = it * 256 + t;
        int l = idx >> 3, q = idx & 7;       // 8 channels per thread
        __align__(16) __half hh[8], hl[8];
#pragma unroll
        for (int i = 0; i < 8; ++i) split_hl(sx[q * 8 + i][l], hh[i], hl[i]);
        *((uint4*)&g_hh[b][j * 64 + l][0] + q) = *(uint4*)hh;
        *((uint4*)&g_hl[b][j * 64 + l][0] + q) = *(uint4*)hl;
    }
}

// ---------- prep: W -> padded fp16 hi/lo, grid (160) ----------
__global__ __launch_bounds__(256) void prep_W(const float* __restrict__ W) {
    int idx = blockIdx.x * 256 + threadIdx.x;   // 0..40959
    int o = idx / CIN, i = idx - o * CIN;
    float v = (o < 64) ? W[o * CIN + i] : 0.f;
    __half hi, lo;
    split_hl(v, hi, lo);
    g_Wh[o][i] = hi;
    g_Wl[o][i] = lo;
}

// ---------------- tcgen05 plumbing (expanded only on 'a'-arch pass) ------------
__device__ __forceinline__ uint32_t smem_u32(const void* p) {
    uint32_t a;
    asm("{ .reg .u64 t; cvta.to.shared.u64 t, %1; cvt.u32.u64 %0, t; }" : "=r"(a) : "l"(p));
    return a;
}
#if HAVE_TC
__device__ __forceinline__ uint32_t elect1() {
    uint32_t p;
    asm volatile("{\n\t.reg .pred p;\n\telect.sync _|p, 0xFFFFFFFF;\n\tselp.b32 %0, 1, 0, p;\n\t}"
                 : "=r"(p));
    return p;
}
static constexpr uint64_t DESC_SW128 =
    (uint64_t(2) << 61) | (uint64_t(1) << 46) | (uint64_t(64) << 32) | (uint64_t(1) << 16);
__device__ __forceinline__ uint64_t mk_desc(uint32_t a) {
    return DESC_SW128 | ((uint64_t)(a >> 4) & 0x3FFF);
}
#define MBAR_INIT(a, c) asm volatile("mbarrier.init.shared.b64 [%0], %1;" :: "r"(a), "r"(c) : "memory")
#define MBAR_INVAL(a)   asm volatile("mbarrier.inval.shared.b64 [%0];" :: "r"(a) : "memory")
#define MBAR_WAIT(a, par) do {                                                     \
    uint32_t _m = (a), _p = (par), _d;                                             \
    asm volatile("{\n\t.reg .pred p;\n\t"                                          \
        "mbarrier.try_wait.parity.acquire.cta.shared::cta.b64 p, [%1], %2;\n\t"    \
        "selp.b32 %0, 1, 0, p;\n\t}" : "=r"(_d) : "r"(_m), "r"(_p) : "memory");    \
    if (!_d) {                                                                     \
        asm volatile("{\n\t.reg .pred P1;\n\t"                                     \
            "WL_%=:\n\t"                                                           \
            "mbarrier.try_wait.parity.acquire.cta.shared::cta.b64 P1, [%0], %1, 0x989680;\n\t" \
            "@P1 bra.uni WD_%=;\n\tbra.uni WL_%=;\n\tWD_%=:\n\t}"                  \
            :: "r"(_m), "r"(_p) : "memory");                                       \
    }                                                                              \
} while (0)
#define TC_ALLOC(sm, n) \
    asm volatile("tcgen05.alloc.cta_group::1.sync.aligned.shared::cta.b32 [%0], %1;" :: "r"(sm), "r"(n) : "memory")
#define TC_DEALLOC(t, n) \
    asm volatile("tcgen05.dealloc.cta_group::1.sync.aligned.b32 %0, %1;" :: "r"(t), "r"(n))
#define TC_COMMIT(mb) \
    asm volatile("tcgen05.commit.cta_group::1.mbarrier::arrive::one.shared::cluster.b64 [%0];" :: "r"(mb) : "memory")
#define TC_WAIT_LD()     asm volatile("tcgen05.wait::ld.sync.aligned;" ::: "memory")
#define TC_FENCE_AFTER() asm volatile("tcgen05.fence::after_thread_sync;" ::: "memory")

#define TC_LD_X32(r, ta)                                                            \
    asm volatile("tcgen05.ld.sync.aligned.32x32b.x32.b32 "                          \
        "{%0, %1, %2, %3, %4, %5, %6, %7, %8, %9, %10, %11, %12, %13, %14, %15, "   \
        " %16, %17, %18, %19, %20, %21, %22, %23, %24, %25, %26, %27, %28, %29, %30, %31}, [%32];" \
        : "=r"((r)[0]), "=r"((r)[1]), "=r"((r)[2]), "=r"((r)[3]),                   \
          "=r"((r)[4]), "=r"((r)[5]), "=r"((r)[6]), "=r"((r)[7]),                   \
          "=r"((r)[8]), "=r"((r)[9]), "=r"((r)[10]), "=r"((r)[11]),                 \
          "=r"((r)[12]), "=r"((r)[13]), "=r"((r)[14]), "=r"((r)[15]),               \
          "=r"((r)[16]), "=r"((r)[17]), "=r"((r)[18]), "=r"((r)[19]),               \
          "=r"((r)[20]), "=r"((r)[21]), "=r"((r)[22]), "=r"((r)[23]),               \
          "=r"((r)[24]), "=r"((r)[25]), "=r"((r)[26]), "=r"((r)[27]),               \
          "=r"((r)[28]), "=r"((r)[29]), "=r"((r)[30]), "=r"((r)[31])                \
        : "r"(ta))

// f16 SS MMA, cg1, M=128, N=64 (field layout verified vs bf16 0x8080490)
#define IDESC_F16 0x8100010u
__device__ __forceinline__ void mma16(uint32_t d, uint64_t ad, uint64_t bd, uint32_t en) {
    asm volatile("{\n\t.reg .pred p;\n\tsetp.ne.u32 p, %3, 0;\n\t"
        "tcgen05.mma.cta_group::1.kind::f16 [%0], %1, %2, %4, {%5, %5, %5, %5}, p;\n\t}"
        :: "r"(d), "l"(ad), "l"(bd), "r"(en), "r"(IDESC_F16), "r"(0u) : "memory");
}

// async-copy R rows x 128B from global into SW128 smem tile
template <int R>
__device__ __forceinline__ void ld_tile(uint32_t dst, const __half* src, int stride_h) {
    const char* s8 = (const char*)src;
    long sb = (long)stride_h * 2;
#pragma unroll
    for (int u = 0; u < (R * 8) / 256; ++u) {
        int idx = u * 256 + threadIdx.x;
        int r = idx >> 3, q = idx & 7;
        const void* sp = s8 + (long)r * sb + q * 16;
        uint32_t off = r * 128 + q * 16;
        uint32_t d = dst + (off ^ ((off >> 3) & 0x70));
        asm volatile("cp.async.cg.shared.global [%0], [%1], 16;" :: "r"(d), "l"(sp));
    }
}

__device__ __forceinline__ void load_chunk(uint32_t sb, int ck,
                                           const __half* Ah, const __half* Al, int astr,
                                           const __half* Bh, const __half* Bl, int bstr) {
    ld_tile<128>(sb,         Ah + ck * 64, astr);
    ld_tile<128>(sb + 16384, Al + ck * 64, astr);
    ld_tile<256>(sb + 32768, Bh + ck * 64, bstr);
    ld_tile<256>(sb + 65536, Bl + ck * 64, bstr);
    asm volatile("cp.async.commit_group;" ::: "memory");
}

// SINGLE-stage 3-term mainloop (2 CTAs/SM hide the intra-CTA serialization);
// D = 128x256 fp32 in TMEM cols [0,256)
template <int NC>
__device__ __forceinline__ void gemm_main(uint32_t dynb, uint32_t mb, uint32_t tmem,
                                          const __half* Ah, const __half* Al, int astr,
                                          const __half* Bh, const __half* Bl, int bstr) {
    load_chunk(dynb, 0, Ah, Al, astr, Bh, Bl, bstr);
    int ph = 0;
#pragma unroll 1
    for (int i = 0; i < NC; ++i) {
        asm volatile("cp.async.wait_group 0;" ::: "memory");
        asm volatile("fence.proxy.async.shared::cta;" ::: "memory");
        __syncthreads();
        if (threadIdx.x < 32 && elect1()) {
            uint64_t dAh = mk_desc(dynb), dAl = mk_desc(dynb + 16384);
            uint64_t dBh = mk_desc(dynb + 32768), dBl = mk_desc(dynb + 65536);
#pragma unroll
            for (int t = 0; t < 3; ++t) {          // Ah*Bh, Ah*Bl, Al*Bh
                uint64_t ad = (t == 2) ? dAl : dAh;
                uint64_t bd = (t == 1) ? dBl : dBh;
#pragma unroll
                for (int ks = 0; ks < 4; ++ks)
#pragma unroll
                    for (int ng = 0; ng < 4; ++ng) {
                        uint32_t en = !(i == 0 && t == 0 && ks == 0);
                        mma16(tmem + ng * 64, ad + ks * 2, bd + ng * 512 + ks * 2, en);
                    }
            }
            TC_COMMIT(mb);
        }
        // all threads wait for MMA of chunk i to finish reading smem
        MBAR_WAIT(mb, ph);
        ph ^= 1;
        if (i + 1 < NC)
            load_chunk(dynb, i + 1, Ah, Al, astr, Bh, Bl, bstr);
    }
    TC_FENCE_AFTER();
}
#endif  // HAVE_TC

#define STG 98304  // single stage: Ah 16K | Al 16K | Bh 32K | Bl 32K

// ---------- kernel: A^2 on tensor cores; grid (1, mt=2, b*2+s2=32) -------------
__global__ __launch_bounds__(256, 2) void k_sq() {
    int mt = blockIdx.y, bz = blockIdx.z;
    int b = bz >> 1, s2 = bz & 1;
#if HAVE_TC
    extern __shared__ char dyn[];
    __shared__ uint32_t s_ctrl[1];
    __shared__ __align__(8) unsigned long long s_mb[1];

    uint32_t ctrl = smem_u32(s_ctrl), mb = smem_u32(s_mb);
    if (threadIdx.x < 32) TC_ALLOC(ctrl, 256);
    if (threadIdx.x == 0) MBAR_INIT(mb, 1);
    __syncthreads();
    uint32_t tmem;
    asm volatile("ld.shared.b32 %0, [%1];" : "=r"(tmem) : "r"(ctrl));
    uint32_t dynb = (smem_u32(dyn) + 1023u) & ~1023u;

    gemm_main<4>(dynb, mb, tmem,
                 &g_Ah[b][2 * s2][mt * 128][0], &g_Al[b][2 * s2][mt * 128][0], KP,
                 &g_ATh[b][s2][0][0], &g_ATl[b][s2][0][0], KP);

    int wid = threadIdx.x >> 5, lane = threadIdx.x & 31;
    if (wid < 4) {
        int j = mt * 128 + wid * 32 + lane;
#pragma unroll 1
        for (int q = 0; q < 8; ++q) {
            __align__(16) uint32_t r[32];
            TC_LD_X32(r, tmem + q * 32);
            TC_WAIT_LD();
            __align__(16) __half hh[32], hl[32];
#pragma unroll
            for (int i = 0; i < 32; ++i) split_hl(__uint_as_float(r[i]), hh[i], hl[i]);
            uint4* dh = (uint4*)&g_Ah[b][2 * s2 + 1][j][q * 32];
            uint4* dl = (uint4*)&g_Al[b][2 * s2 + 1][j][q * 32];
#pragma unroll
            for (int u = 0; u < 4; ++u) { dh[u] = ((uint4*)hh)[u]; dl[u] = ((uint4*)hl)[u]; }
        }
    }
    __syncthreads();
    if (threadIdx.x == 0) MBAR_INVAL(mb);
    if (threadIdx.x < 32) TC_DEALLOC(tmem, 256);
#else
    // FFMA fallback: A^2 tile rows [mt*128,+128) x cols [0,256)
    __shared__ float As[16 * 68];
    __shared__ float Bs[16 * 64];
    int t = threadIdx.x;
    int tx = t & 15, ty = t >> 4;
    int la_k = t & 15, la_j = t >> 4;
    int lb_l = t & 63, lb_k = t >> 6;

    for (int jt = 0; jt < 2; ++jt) {
        int row0 = mt * 128 + jt * 64;
        for (int ct = 0; ct < 4; ++ct) {
            int col0 = ct * 64;
            unsigned long long zz = pack2(0.f, 0.f);
            unsigned long long acc[4][2];
#pragma unroll
            for (int u = 0; u < 4; ++u) { acc[u][0] = zz; acc[u][1] = zz; }
            for (int k0 = 0; k0 < KP; k0 += 16) {
                __syncthreads();
#pragma unroll
                for (int p = 0; p < 4; ++p) {
                    int jj = la_j + p * 16;
                    As[la_k * 68 + jj] =
                        __half2float(g_Ah[b][2 * s2][row0 + jj][k0 + la_k]) +
                        __half2float(g_Al[b][2 * s2][row0 + jj][k0 + la_k]);
                }
#pragma unroll
                for (int p = 0; p < 4; ++p) {
                    int kk = lb_k + p * 4;
                    Bs[kk * 64 + lb_l] =
                        __half2float(g_ATh[b][s2][k0 + kk][col0 + lb_l]) +
                        __half2float(g_ATl[b][s2][k0 + kk][col0 + lb_l]);
                }
                __syncthreads();
                mm_tile(As, Bs, acc, ty, tx);
            }
#pragma unroll
            for (int u = 0; u < 4; ++u) {
                int gj = row0 + ty * 4 + u;
                float2 p01 = unpack2(acc[u][0]);
                float2 p23 = unpack2(acc[u][1]);
                float vals[4] = {p01.x, p01.y, p23.x, p23.y};
#pragma unroll
                for (int v = 0; v < 4; ++v) {
                    __half hi, lo;
                    split_hl(vals[v], hi, lo);
                    g_Ah[b][2 * s2 + 1][gj][col0 + tx * 4 + v] = hi;
                    g_Al[b][2 * s2 + 1][gj][col0 + tx * 4 + v] = lo;
                }
            }
            __syncthreads();
        }
    }
#endif
}

// ---------- kernel: diffusion, grid (nt=16, mt=2, b*4+s=64) --------------------
__global__ __launch_bounds__(256, 2) void k_diffuse(const float* __restrict__ x) {
    int nt = blockIdx.x, mt = blockIdx.y, bz = blockIdx.z;
    int b = bz >> 2, s = bz & 3;
#if HAVE_TC
    extern __shared__ char dyn[];
    __shared__ uint32_t s_ctrl[1];
    __shared__ __align__(8) unsigned long long s_mb[1];

    uint32_t ctrl = smem_u32(s_ctrl), mb = smem_u32(s_mb);
    if (threadIdx.x < 32) TC_ALLOC(ctrl, 256);
    if (threadIdx.x == 0) MBAR_INIT(mb, 1);
    __syncthreads();
    uint32_t tmem;
    asm volatile("ld.shared.b32 %0, [%1];" : "=r"(tmem) : "r"(ctrl));
    uint32_t dynb = (smem_u32(dyn) + 1023u) & ~1023u;

    gemm_main<4>(dynb, mb, tmem,
                 &g_Ah[b][s][mt * 128][0], &g_Al[b][s][mt * 128][0], KP,
                 &g_Xh[b][nt * 256][0], &g_Xl[b][nt * 256][0], KP);

    int wid = threadIdx.x >> 5, lane = threadIdx.x & 31;
    if (wid < 4) {  // warps 0-3 cover the 128 TMEM lanes (rows j)
        int j = mt * 128 + wid * 32 + lane;
        bool ok = (j < K_DIM);
        int ch0 = 64 + s * 64;
#pragma unroll 1
        for (int q = 0; q < 8; ++q) {
            __align__(16) uint32_t r[32];
            TC_LD_X32(r, tmem + q * 32);
            TC_WAIT_LD();
            if (ok) {
                int l = nt * 4 + (q >> 1), c0 = (q & 1) * 32;
                __align__(16) __half hh[32], hl[32];
#pragma unroll
                for (int i = 0; i < 32; ++i)
                    split_hl(__uint_as_float(r[i]), hh[i], hl[i]);
                uint4* dh = (uint4*)&g_hh[b][j * 64 + l][ch0 + c0];
                uint4* dl = (uint4*)&g_hl[b][j * 64 + l][ch0 + c0];
#pragma unroll
                for (int u = 0; u < 4; ++u) { dh[u] = ((uint4*)hh)[u]; dl[u] = ((uint4*)hl)[u]; }
            }
        }
    }
    __syncthreads();
    if (threadIdx.x == 0) MBAR_INVAL(mb);
    if (threadIdx.x < 32) TC_DEALLOC(tmem, 256);
#else
    // FFMA fallback (never runs on GB300; correctness-preserving)
    __shared__ float As[16 * 68];
    __shared__ float Bs[16 * 64];
    int t = threadIdx.x;
    int tx = t & 15, ty = t >> 4;
    int la_k = t & 15, la_j = t >> 4;
    int lb_l = t & 63, lb_k = t >> 6;
    int ch0 = 64 + s * 64;

    for (int jt = 0; jt < 2; ++jt) {
        int row0 = mt * 128 + jt * 64;
        if (row0 >= K_DIM) break;
        for (int ct = 0; ct < 4; ++ct) {
            int c = nt * 4 + ct;
            const float* X = x + (long)b * CKL + (long)c * KL;
            unsigned long long zz = pack2(0.f, 0.f);
            unsigned long long acc[4][2];
#pragma unroll
            for (int u = 0; u < 4; ++u) { acc[u][0] = zz; acc[u][1] = zz; }
            for (int k0 = 0; k0 < K_DIM; k0 += 16) {
                __syncthreads();
#pragma unroll
                for (int p = 0; p < 4; ++p) {
                    int jj = la_j + p * 16;
                    int gj = row0 + jj, gk = k0 + la_k;
                    As[la_k * 68 + jj] =
                        (gj < KP && gk < KP)
                            ? (__half2float(g_Ah[b][s][gj][gk]) +
                               __half2float(g_Al[b][s][gj][gk]))
                            : 0.f;
                }
#pragma unroll
                for (int p = 0; p < 4; ++p) {
                    int kk = lb_k + p * 4;
                    int gk = k0 + kk;
                    Bs[kk * 64 + lb_l] = (gk < K_DIM) ? X[gk * 64 + lb_l] : 0.f;
                }
                __syncthreads();
                mm_tile(As, Bs, acc, ty, tx);
            }
#pragma unroll
            for (int u = 0; u < 4; ++u) {
                int gj = row0 + ty * 4 + u;
                if (gj < K_DIM) {
                    float2 p01 = unpack2(acc[u][0]);
                    float2 p23 = unpack2(acc[u][1]);
                    float vals[4] = {p01.x, p01.y, p23.x, p23.y};
#pragma unroll
                    for (int v = 0; v < 4; ++v) {
                        int l = tx * 4 + v;
                        __half hi, lo;
                        split_hl(vals[v], hi, lo);
                        g_hh[b][gj * 64 + l][ch0 + c] = hi;
                        g_hl[b][gj * 64 + l][ch0 + c] = lo;
                    }
                }
            }
            __syncthreads();
        }
    }
#endif
}

// ---------- kernel: conv y = W @ h + bias, grid (nt=52, b=16) ------------------
__global__ __launch_bounds__(256, 2) void k_conv(const float* __restrict__ W,
                                                 const float* __restrict__ bias,
                                                 float* __restrict__ y) {
    int nt = blockIdx.x, b = blockIdx.y;
#if HAVE_TC
    extern __shared__ char dyn[];
    __shared__ uint32_t s_ctrl[1];
    __shared__ __align__(8) unsigned long long s_mb[1];

    uint32_t ctrl = smem_u32(s_ctrl), mb = smem_u32(s_mb);
    if (threadIdx.x < 32) TC_ALLOC(ctrl, 256);
    if (threadIdx.x == 0) MBAR_INIT(mb, 1);
    __syncthreads();
    uint32_t tmem;
    asm volatile("ld.shared.b32 %0, [%1];" : "=r"(tmem) : "r"(ctrl));
    uint32_t dynb = (smem_u32(dyn) + 1023u) & ~1023u;

    gemm_main<5>(dynb, mb, tmem,
                 &g_Wh[0][0], &g_Wl[0][0], CIN,
                 &g_hh[b][nt * 256][0], &g_hl[b][nt * 256][0], CIN);

    int wid = threadIdx.x >> 5, lane = threadIdx.x & 31;
    if (wid < 2) {  // TMEM lanes 0..63 = output channels
        int o = wid * 32 + lane;
        float bv = bias[o];
        float* yp = y + (long)b * CKL + (long)o * KL;
#pragma unroll 1
        for (int q = 0; q < 8; ++q) {
            __align__(16) uint32_t r[32];
            TC_LD_X32(r, tmem + q * 32);
            TC_WAIT_LD();
            int n0 = nt * 256 + q * 32;
            if (n0 < KL) {
                __align__(16) float v[32];
#pragma unroll
                for (int i = 0; i < 32; ++i) v[i] = __uint_as_float(r[i]) + bv;
                uint4* dst = (uint4*)(yp + n0);
#pragma unroll
                for (int u = 0; u < 8; ++u) dst[u] = ((uint4*)v)[u];
            }
        }
    }
    __syncthreads();
    if (threadIdx.x == 0) MBAR_INVAL(mb);
    if (threadIdx.x < 32) TC_DEALLOC(tmem, 256);
#else
    // FFMA fallback
    __shared__ float As[16 * 68];
    __shared__ float Bs[16 * 64];
    int t = threadIdx.x;
    int tx = t & 15, ty = t >> 4;
    int la_k = t & 15, la_j = t >> 4;
    int lb_l = t & 63, lb_k = t >> 6;

    for (int sub = 0; sub < 4; ++sub) {
        int n0 = nt * 256 + sub * 64;
        if (n0 >= KL) break;
        unsigned long long acc[4][2];
#pragma unroll
        for (int u = 0; u < 4; ++u) {
            float bv = bias[ty * 4 + u];
            acc[u][0] = pack2(bv, bv);
            acc[u][1] = pack2(bv, bv);
        }
        for (int i0 = 0; i0 < CIN; i0 += 16) {
            __syncthreads();
#pragma unroll
            for (int p = 0; p < 4; ++p) {
                int o = la_j + p * 16;
                As[la_k * 68 + o] = (o < 64) ? W[o * CIN + i0 + la_k] : 0.f;
            }
#pragma unroll
            for (int p = 0; p < 4; ++p) {
                int ii = lb_k + p * 4;
                int i = i0 + ii;
                int n = n0 + lb_l;
                Bs[ii * 64 + lb_l] = __half2float(g_hh[b][n][i]) +
                                     __half2float(g_hl[b][n][i]);
            }
            __syncthreads();
            mm_tile(As, Bs, acc, ty, tx);
        }
#pragma unroll
        for (int u = 0; u < 4; ++u) {
            int o = ty * 4 + u;
            if (o < 64) {
                float2 p01 = unpack2(acc[u][0]);
                float2 p23 = unpack2(acc[u][1]);
                float4 ov = make_float4(p01.x, p01.y, p23.x, p23.y);
                *(float4*)(y + (long)b * CKL + (long)o * KL + n0 + tx * 4) = ov;
            }
        }
        __syncthreads();
    }
#endif
}

extern "C" void kernel_launch(void* const* d_in, const int* in_sizes, int n_in,
                              void* d_out, int out_size) {
    const float* x    = (const float*)d_in[0];   // (16, 64, 13248)
    const float* a0   = (const float*)d_in[1];   // (16, 207, 207)
    const float* a1   = (const float*)d_in[2];   // (16, 207, 207)
    const float* W    = (const float*)d_in[3];   // (64, 320)
    const float* bias = (const float*)d_in[4];   // (64,)
    float* y = (float*)d_out;                    // (16, 64, 13248)

    cudaFuncSetAttribute(k_sq, cudaFuncAttributeMaxDynamicSharedMemorySize,
                         STG + 1024);
    cudaFuncSetAttribute(k_diffuse, cudaFuncAttributeMaxDynamicSharedMemorySize,
                         STG + 1024);
    cudaFuncSetAttribute(k_conv, cudaFuncAttributeMaxDynamicSharedMemorySize,
                         STG + 1024);
    cudaFuncSetAttribute(prep_X, cudaFuncAttributeMaxDynamicSharedMemorySize,
                         207 * 68 * 4);

    dim3 blk(256);
    prep_A<<<dim3(256, 32), blk>>>(a0, a1);
    prep_AT<<<dim3(4, 4, 32), blk>>>(a0, a1);
    k_sq<<<dim3(1, 2, 32), blk, STG + 1024>>>();
    prep_X<<<dim3(64, 16), dim3(512), 207 * 68 * 4>>>(x);
    prep_xh<<<dim3(207, 16), blk>>>(x);
    prep_W<<<dim3(160), blk>>>(W);
    k_diffuse<<<dim3(16, 2, 64), blk, STG + 1024>>>(x);
    k_conv<<<dim3(52, 16), blk, STG + 1024>>>(W, bias, y);
}

// round 9
// speedup vs baseline: 1.0538x; 1.0538x over previous
#include <cuda_runtime.h>
#include <cuda_fp16.h>
#include <cstdint>

#define B_DIM 16
#define C_DIM 64
#define K_DIM 207
#define L_DIM 64
#define KL 13248          // K_DIM * L_DIM
#define CKL (C_DIM * KL)  // 847872
#define KK2 42849         // K_DIM * K_DIM
#define CLDIM 4096        // C_DIM * L_DIM
#define KP 256            // padded K / M for tensor path
#define CIN 320           // conv input channels
#define NH 13312          // padded (j,l) rows = 52*256

// Does this device-compilation pass support tcgen05? ('a'-arch targets only)
#if defined(__CUDA_ARCH_FEAT_SM103_ALL) || defined(__CUDA_ARCH_FEAT_SM100_ALL) || \
    defined(__CUDA_ARCH_FEAT_SM101_ALL)
#define HAVE_TC 1
#else
#define HAVE_TC 0
#endif

// Scratch (device globals: allocation-free per harness rules; zero-initialized)
__device__ __half g_Ah[B_DIM][4][KP][KP];             // A hi; s:0=A0,1=A0^2,2=A1,3=A1^2
__device__ __half g_Al[B_DIM][4][KP][KP];             // A lo
__device__ __half g_ATh[B_DIM][2][KP][KP];            // A^T hi (for squaring), s2:0=A0,1=A1
__device__ __half g_ATl[B_DIM][2][KP][KP];            // A^T lo
__device__ __half g_Xh[B_DIM][CLDIM][KP];             // X^T hi: [b][l*64+c][k]
__device__ __half g_Xl[B_DIM][CLDIM][KP];             // X^T lo
__device__ __half g_hh[B_DIM][NH][CIN];               // h=[x;G] hi: [b][j*64+l][ch]
__device__ __half g_hl[B_DIM][NH][CIN];               // h lo
__device__ __half g_Wh[128][CIN];                     // W hi, rows 64..127 zero
__device__ __half g_Wl[128][CIN];                     // W lo

// ---------- packed f32x2 helpers ----------
__device__ __forceinline__ unsigned long long pack2(float lo, float hi) {
    unsigned long long r;
    asm("mov.b64 %0, {%1, %2};" : "=l"(r) : "f"(lo), "f"(hi));
    return r;
}
__device__ __forceinline__ void fma2(unsigned long long& d, unsigned long long a,
                                     unsigned long long b) {
    asm("fma.rn.f32x2 %0, %1, %2, %0;" : "+l"(d) : "l"(a), "l"(b));
}
__device__ __forceinline__ float2 unpack2(unsigned long long v) {
    float2 f;
    asm("mov.b64 {%0, %1}, %2;" : "=f"(f.x), "=f"(f.y) : "l"(v));
    return f;
}
__device__ __forceinline__ void split_hl(float v, __half& hi, __half& lo) {
    hi = __float2half_rn(v);
    lo = __float2half_rn(v - __half2float(hi));
}

// ---------- FFMA 64x64 microkernel (fallback paths only) ----------
__device__ __forceinline__ void mm_tile(const float* __restrict__ As,
                                        const float* __restrict__ Bs,
                                        unsigned long long (&acc)[4][2],
                                        int ty, int tx) {
#pragma unroll
    for (int kk = 0; kk < 16; ++kk) {
        float4 av = *(const float4*)(As + kk * 68 + ty * 4);
        float4 bv = *(const float4*)(Bs + kk * 64 + tx * 4);
        unsigned long long b01 = pack2(bv.x, bv.y);
        unsigned long long b23 = pack2(bv.z, bv.w);
        unsigned long long a;
        a = pack2(av.x, av.x); fma2(acc[0][0], a, b01); fma2(acc[0][1], a, b23);
        a = pack2(av.y, av.y); fma2(acc[1][0], a, b01); fma2(acc[1][1], a, b23);
        a = pack2(av.z, av.z); fma2(acc[2][0], a, b01); fma2(acc[2][1], a, b23);
        a = pack2(av.w, av.w); fma2(acc[3][0], a, b01); fma2(acc[3][1], a, b23);
    }
}

// ---------- prep: A (s=0,2) -> fp16 hi/lo, zero-padded; grid (256, 32) ----------
__global__ __launch_bounds__(256) void prep_A(const float* __restrict__ a0,
                                              const float* __restrict__ a1) {
    int j = blockIdx.x;            // 0..255
    int bz = blockIdx.y;           // b*2+s2
    int b = bz >> 1, s2 = bz & 1;
    int k = threadIdx.x;
    const float* src = (s2 ? a1 : a0) + b * KK2;
    float v = (j < K_DIM && k < K_DIM) ? src[j * K_DIM + k] : 0.f;
    __half hi, lo;
    split_hl(v, hi, lo);
    g_Ah[b][2 * s2][j][k] = hi;
    g_Al[b][2 * s2][j][k] = lo;
}

// ---------- prep: A^T (s2=0,1) via smem transpose; grid (4, 4, 32) ----------
__global__ __launch_bounds__(256) void prep_AT(const float* __restrict__ a0,
                                               const float* __restrict__ a1) {
    __shared__ float s[64][65];
    int kt = blockIdx.x, jt = blockIdx.y, bz = blockIdx.z;
    int b = bz >> 1, s2 = bz & 1;
    const float* src = (s2 ? a1 : a0) + b * KK2;
    int t = threadIdx.x;
    int col = t & 63, row4 = t >> 6;
#pragma unroll
    for (int it = 0; it < 16; ++it) {
        int lj = it * 4 + row4;
        int j = jt * 64 + lj, k = kt * 64 + col;
        s[lj][col] = (j < K_DIM && k < K_DIM) ? src[j * K_DIM + k] : 0.f;
    }
    __syncthreads();
#pragma unroll
    for (int it = 0; it < 16; ++it) {
        int r = it * 4 + row4;          // local k
        float v = s[col][r];            // AT[k][j] = A[j][k]
        __half hi, lo;
        split_hl(v, hi, lo);
        g_ATh[b][s2][kt * 64 + r][jt * 64 + col] = hi;
        g_ATl[b][s2][kt * 64 + r][jt * 64 + col] = lo;
    }
}

// ---------- prep: transpose X to [b][l*64+c][k] fp16 hi/lo; 512 thr, float4 ----
__global__ __launch_bounds__(512) void prep_X(const float* __restrict__ x) {
    extern __shared__ float s_x[];     // [207][68]
    int c = blockIdx.x, b = blockIdx.y;
    const float* xp = x + (long)b * CKL + (long)c * KL;
    int t = threadIdx.x;
    // 13248 floats = 3312 float4; layout [k][l], row pad 68 (272B, 16B-aligned)
#pragma unroll
    for (int it = 0; it < 7; ++it) {
        int idx = it * 512 + t;
        if (idx < 3312) {
            float4 v = ((const float4*)xp)[idx];
            int k = idx >> 4, l4 = (idx & 15) * 4;
            *(float4*)&s_x[k * 68 + l4] = v;
        }
    }
    __syncthreads();
    int kq = t >> 6, l = t & 63;       // kq 0..7, each handles 32 k
    __align__(16) __half hh[32], hl[32];
#pragma unroll
    for (int i = 0; i < 32; ++i) {
        int k = kq * 32 + i;
        float v = (k < K_DIM) ? s_x[k * 68 + l] : 0.f;
        split_hl(v, hh[i], hl[i]);
    }
    uint4* dh = (uint4*)&g_Xh[b][l * 64 + c][kq * 32];
    uint4* dl = (uint4*)&g_Xl[b][l * 64 + c][kq * 32];
#pragma unroll
    for (int i = 0; i < 4; ++i) { dh[i] = ((uint4*)hh)[i]; dl[i] = ((uint4*)hl)[i]; }
}

// ---------- prep: x -> channels [0,64) of g_h (hi/lo), grid (207, 16) ----------
__global__ __launch_bounds__(256) void prep_xh(const float* __restrict__ x) {
    __shared__ float sx[64][68];
    int j = blockIdx.x, b = blockIdx.y;
    int t = threadIdx.x;
    const float* xp = x + (long)b * CKL + j * 64;
#pragma unroll
    for (int it = 0; it < 4; ++it) {
        int idx = it * 256 + t;        // float4 index within [c][l]
        int c = idx >> 4, l4 = (idx & 15) * 4;
        float4 v = *(const float4*)(xp + (long)c * KL + l4);
        *(float4*)&sx[c][l4] = v;
    }
    __syncthreads();
#pragma unroll
    for (int it = 0; it < 2; ++it) {
        int idx = it * 256 + t;
        int l = idx >> 3, q = idx & 7;       // 8 channels per thread
        __align__(16) __half hh[8], hl[8];
#pragma unroll
        for (int i = 0; i < 8; ++i) split_hl(sx[q * 8 + i][l], hh[i], hl[i]);
        *((uint4*)&g_hh[b][j * 64 + l][0] + q) = *(uint4*)hh;
        *((uint4*)&g_hl[b][j * 64 + l][0] + q) = *(uint4*)hl;
    }
}

// ---------- prep: W -> padded fp16 hi/lo, grid (160) ----------
__global__ __launch_bounds__(256) void prep_W(const float* __restrict__ W) {
    int idx = blockIdx.x * 256 + threadIdx.x;   // 0..40959
    int o = idx / CIN, i = idx - o * CIN;
    float v = (o < 64) ? W[o * CIN + i] : 0.f;
    __half hi, lo;
    split_hl(v, hi, lo);
    g_Wh[o][i] = hi;
    g_Wl[o][i] = lo;
}

// ---------------- tcgen05 plumbing (expanded only on 'a'-arch pass) ------------
__device__ __forceinline__ uint32_t smem_u32(const void* p) {
    uint32_t a;
    asm("{ .reg .u64 t; cvta.to.shared.u64 t, %1; cvt.u32.u64 %0, t; }" : "=r"(a) : "l"(p));
    return a;
}
#if HAVE_TC
__device__ __forceinline__ uint32_t elect1() {
    uint32_t p;
    asm volatile("{\n\t.reg .pred p;\n\telect.sync _|p, 0xFFFFFFFF;\n\tselp.b32 %0, 1, 0, p;\n\t}"
                 : "=r"(p));
    return p;
}
static constexpr uint64_t DESC_SW128 =
    (uint64_t(2) << 61) | (uint64_t(1) << 46) | (uint64_t(64) << 32) | (uint64_t(1) << 16);
__device__ __forceinline__ uint64_t mk_desc(uint32_t a) {
    return DESC_SW128 | ((uint64_t)(a >> 4) & 0x3FFF);
}
#define MBAR_INIT(a, c) asm volatile("mbarrier.init.shared.b64 [%0], %1;" :: "r"(a), "r"(c) : "memory")
#define MBAR_INVAL(a)   asm volatile("mbarrier.inval.shared.b64 [%0];" :: "r"(a) : "memory")
#define MBAR_WAIT(a, par) do {                                                     \
    uint32_t _m = (a), _p = (par), _d;                                             \
    asm volatile("{\n\t.reg .pred p;\n\t"                                          \
        "mbarrier.try_wait.parity.acquire.cta.shared::cta.b64 p, [%1], %2;\n\t"    \
        "selp.b32 %0, 1, 0, p;\n\t}" : "=r"(_d) : "r"(_m), "r"(_p) : "memory");    \
    if (!_d) {                                                                     \
        asm volatile("{\n\t.reg .pred P1;\n\t"                                     \
            "WL_%=:\n\t"                                                           \
            "mbarrier.try_wait.parity.acquire.cta.shared::cta.b64 P1, [%0], %1, 0x989680;\n\t" \
            "@P1 bra.uni WD_%=;\n\tbra.uni WL_%=;\n\tWD_%=:\n\t}"                  \
            :: "r"(_m), "r"(_p) : "memory");                                       \
    }                                                                              \
} while (0)
#define TC_ALLOC(sm, n) \
    asm volatile("tcgen05.alloc.cta_group::1.sync.aligned.shared::cta.b32 [%0], %1;" :: "r"(sm), "r"(n) : "memory")
#define TC_DEALLOC(t, n) \
    asm volatile("tcgen05.dealloc.cta_group::1.sync.aligned.b32 %0, %1;" :: "r"(t), "r"(n))
#define TC_COMMIT(mb) \
    asm volatile("tcgen05.commit.cta_group::1.mbarrier::arrive::one.shared::cluster.b64 [%0];" :: "r"(mb) : "memory")
#define TC_WAIT_LD()     asm volatile("tcgen05.wait::ld.sync.aligned;" ::: "memory")
#define TC_FENCE_AFTER() asm volatile("tcgen05.fence::after_thread_sync;" ::: "memory")

#define TC_LD_X32(r, ta)                                                            \
    asm volatile("tcgen05.ld.sync.aligned.32x32b.x32.b32 "                          \
        "{%0, %1, %2, %3, %4, %5, %6, %7, %8, %9, %10, %11, %12, %13, %14, %15, "   \
        " %16, %17, %18, %19, %20, %21, %22, %23, %24, %25, %26, %27, %28, %29, %30, %31}, [%32];" \
        : "=r"((r)[0]), "=r"((r)[1]), "=r"((r)[2]), "=r"((r)[3]),                   \
          "=r"((r)[4]), "=r"((r)[5]), "=r"((r)[6]), "=r"((r)[7]),                   \
          "=r"((r)[8]), "=r"((r)[9]), "=r"((r)[10]), "=r"((r)[11]),                 \
          "=r"((r)[12]), "=r"((r)[13]), "=r"((r)[14]), "=r"((r)[15]),               \
          "=r"((r)[16]), "=r"((r)[17]), "=r"((r)[18]), "=r"((r)[19]),               \
          "=r"((r)[20]), "=r"((r)[21]), "=r"((r)[22]), "=r"((r)[23]),               \
          "=r"((r)[24]), "=r"((r)[25]), "=r"((r)[26]), "=r"((r)[27]),               \
          "=r"((r)[28]), "=r"((r)[29]), "=r"((r)[30]), "=r"((r)[31])                \
        : "r"(ta))

// f16 SS MMA, cg1, M=128, N=64 (field layout verified vs bf16 0x8080490)
#define IDESC_F16 0x8100010u
__device__ __forceinline__ void mma16(uint32_t d, uint64_t ad, uint64_t bd, uint32_t en) {
    asm volatile("{\n\t.reg .pred p;\n\tsetp.ne.u32 p, %3, 0;\n\t"
        "tcgen05.mma.cta_group::1.kind::f16 [%0], %1, %2, %4, {%5, %5, %5, %5}, p;\n\t}"
        :: "r"(d), "l"(ad), "l"(bd), "r"(en), "r"(IDESC_F16), "r"(0u) : "memory");
}

// async-copy R rows x 128B from global into SW128 smem tile
template <int R>
__device__ __forceinline__ void ld_tile(uint32_t dst, const __half* src, int stride_h) {
    const char* s8 = (const char*)src;
    long sb = (long)stride_h * 2;
#pragma unroll
    for (int u = 0; u < (R * 8) / 256; ++u) {
        int idx = u * 256 + threadIdx.x;
        int r = idx >> 3, q = idx & 7;
        const void* sp = s8 + (long)r * sb + q * 16;
        uint32_t off = r * 128 + q * 16;
        uint32_t d = dst + (off ^ ((off >> 3) & 0x70));
        asm volatile("cp.async.cg.shared.global [%0], [%1], 16;" :: "r"(d), "l"(sp));
    }
}

__device__ __forceinline__ void load_chunk(uint32_t sb, int ck,
                                           const __half* Ah, const __half* Al, int astr,
                                           const __half* Bh, const __half* Bl, int bstr) {
    ld_tile<128>(sb,         Ah + ck * 64, astr);
    ld_tile<128>(sb + 16384, Al + ck * 64, astr);
    ld_tile<256>(sb + 32768, Bh + ck * 64, bstr);
    ld_tile<256>(sb + 65536, Bl + ck * 64, bstr);
    asm volatile("cp.async.commit_group;" ::: "memory");
}

// double-buffered 3-term mainloop; D = 128x256 fp32 in TMEM cols [0,256)
template <int NC>
__device__ __forceinline__ void gemm_main(uint32_t dynb, uint32_t mb, uint32_t tmem,
                                          const __half* Ah, const __half* Al, int astr,
                                          const __half* Bh, const __half* Bl, int bstr) {
    load_chunk(dynb, 0, Ah, Al, astr, Bh, Bl, bstr);
    int p0 = 0, p1 = 0;
#pragma unroll 1
    for (int i = 0; i < NC; ++i) {
        int q = i & 1;
        asm volatile("cp.async.wait_group 0;" ::: "memory");
        asm volatile("fence.proxy.async.shared::cta;" ::: "memory");
        __syncthreads();
        if (threadIdx.x < 32 && elect1()) {
            uint32_t sb = dynb + q * 98304;
            uint64_t dAh = mk_desc(sb), dAl = mk_desc(sb + 16384);
            uint64_t dBh = mk_desc(sb + 32768), dBl = mk_desc(sb + 65536);
#pragma unroll
            for (int t = 0; t < 3; ++t) {          // Ah*Bh, Ah*Bl, Al*Bh
                uint64_t ad = (t == 2) ? dAl : dAh;
                uint64_t bd = (t == 1) ? dBl : dBh;
#pragma unroll
                for (int ks = 0; ks < 4; ++ks)
#pragma unroll
                    for (int ng = 0; ng < 4; ++ng) {
                        uint32_t en = !(i == 0 && t == 0 && ks == 0);
                        mma16(tmem + ng * 64, ad + ks * 2, bd + ng * 512 + ks * 2, en);
                    }
            }
            TC_COMMIT(mb + q * 8);
        }
        if (i + 1 < NC) {
            int q2 = (i + 1) & 1;
            if (i >= 1) {
                if (q2 == 0) { MBAR_WAIT(mb, p0); p0 ^= 1; }
                else         { MBAR_WAIT(mb + 8, p1); p1 ^= 1; }
            }
            load_chunk(dynb + q2 * 98304, i + 1, Ah, Al, astr, Bh, Bl, bstr);
        }
    }
    MBAR_WAIT(mb, p0);
    MBAR_WAIT(mb + 8, p1);
    TC_FENCE_AFTER();
}
#endif  // HAVE_TC

#define STG 98304  // stage: Ah 16K | Al 16K | Bh 32K | Bl 32K

// ---------- kernel: A^2 on tensor cores; grid (1, mt=2, b*2+s2=32) -------------
__global__ __launch_bounds__(256, 1) void k_sq() {
    int mt = blockIdx.y, bz = blockIdx.z;
    int b = bz >> 1, s2 = bz & 1;
#if HAVE_TC
    extern __shared__ char dyn[];
    __shared__ uint32_t s_ctrl[1];
    __shared__ __align__(8) unsigned long long s_mb[2];

    uint32_t ctrl = smem_u32(s_ctrl), mb = smem_u32(s_mb);
    if (threadIdx.x < 32) TC_ALLOC(ctrl, 256);
    if (threadIdx.x == 0) { MBAR_INIT(mb, 1); MBAR_INIT(mb + 8, 1); }
    __syncthreads();
    uint32_t tmem;
    asm volatile("ld.shared.b32 %0, [%1];" : "=r"(tmem) : "r"(ctrl));
    uint32_t dynb = (smem_u32(dyn) + 1023u) & ~1023u;

    gemm_main<4>(dynb, mb, tmem,
                 &g_Ah[b][2 * s2][mt * 128][0], &g_Al[b][2 * s2][mt * 128][0], KP,
                 &g_ATh[b][s2][0][0], &g_ATl[b][s2][0][0], KP);

    int wid = threadIdx.x >> 5, lane = threadIdx.x & 31;
    if (wid < 4) {
        int j = mt * 128 + wid * 32 + lane;
#pragma unroll 1
        for (int q = 0; q < 8; ++q) {
            __align__(16) uint32_t r[32];
            TC_LD_X32(r, tmem + q * 32);
            TC_WAIT_LD();
            __align__(16) __half hh[32], hl[32];
#pragma unroll
            for (int i = 0; i < 32; ++i) split_hl(__uint_as_float(r[i]), hh[i], hl[i]);
            uint4* dh = (uint4*)&g_Ah[b][2 * s2 + 1][j][q * 32];
            uint4* dl = (uint4*)&g_Al[b][2 * s2 + 1][j][q * 32];
#pragma unroll
            for (int u = 0; u < 4; ++u) { dh[u] = ((uint4*)hh)[u]; dl[u] = ((uint4*)hl)[u]; }
        }
    }
    __syncthreads();
    if (threadIdx.x == 0) { MBAR_INVAL(mb); MBAR_INVAL(mb + 8); }
    if (threadIdx.x < 32) TC_DEALLOC(tmem, 256);
#else
    // FFMA fallback: A^2 tile rows [mt*128,+128) x cols [0,256)
    __shared__ float As[16 * 68];
    __shared__ float Bs[16 * 64];
    int t = threadIdx.x;
    int tx = t & 15, ty = t >> 4;
    int la_k = t & 15, la_j = t >> 4;
    int lb_l = t & 63, lb_k = t >> 6;

    for (int jt = 0; jt < 2; ++jt) {
        int row0 = mt * 128 + jt * 64;
        for (int ct = 0; ct < 4; ++ct) {
            int col0 = ct * 64;
            unsigned long long zz = pack2(0.f, 0.f);
            unsigned long long acc[4][2];
#pragma unroll
            for (int u = 0; u < 4; ++u) { acc[u][0] = zz; acc[u][1] = zz; }
            for (int k0 = 0; k0 < KP; k0 += 16) {
                __syncthreads();
#pragma unroll
                for (int p = 0; p < 4; ++p) {
                    int jj = la_j + p * 16;
                    As[la_k * 68 + jj] =
                        __half2float(g_Ah[b][2 * s2][row0 + jj][k0 + la_k]) +
                        __half2float(g_Al[b][2 * s2][row0 + jj][k0 + la_k]);
                }
#pragma unroll
                for (int p = 0; p < 4; ++p) {
                    int kk = lb_k + p * 4;
                    Bs[kk * 64 + lb_l] =
                        __half2float(g_ATh[b][s2][k0 + kk][col0 + lb_l]) +
                        __half2float(g_ATl[b][s2][k0 + kk][col0 + lb_l]);
                }
                __syncthreads();
                mm_tile(As, Bs, acc, ty, tx);
            }
#pragma unroll
            for (int u = 0; u < 4; ++u) {
                int gj = row0 + ty * 4 + u;
                float2 p01 = unpack2(acc[u][0]);
                float2 p23 = unpack2(acc[u][1]);
                float vals[4] = {p01.x, p01.y, p23.x, p23.y};
#pragma unroll
                for (int v = 0; v < 4; ++v) {
                    __half hi, lo;
                    split_hl(vals[v], hi, lo);
                    g_Ah[b][2 * s2 + 1][gj][col0 + tx * 4 + v] = hi;
                    g_Al[b][2 * s2 + 1][gj][col0 + tx * 4 + v] = lo;
                }
            }
            __syncthreads();
        }
    }
#endif
}

// ---------- kernel: diffusion, grid (smt=8, nt=16, b=16) -----------------------
// blockIdx.x = s*2+mt so the 8 CTAs sharing one B tile are launch-adjacent (L2 reuse)
__global__ __launch_bounds__(256, 1) void k_diffuse(const float* __restrict__ x) {
    int smt = blockIdx.x, nt = blockIdx.y, b = blockIdx.z;
    int s = smt >> 1, mt = smt & 1;
#if HAVE_TC
    extern __shared__ char dyn[];
    __shared__ uint32_t s_ctrl[1];
    __shared__ __align__(8) unsigned long long s_mb[2];

    uint32_t ctrl = smem_u32(s_ctrl), mb = smem_u32(s_mb);
    if (threadIdx.x < 32) TC_ALLOC(ctrl, 256);
    if (threadIdx.x == 0) { MBAR_INIT(mb, 1); MBAR_INIT(mb + 8, 1); }
    __syncthreads();
    uint32_t tmem;
    asm volatile("ld.shared.b32 %0, [%1];" : "=r"(tmem) : "r"(ctrl));
    uint32_t dynb = (smem_u32(dyn) + 1023u) & ~1023u;

    gemm_main<4>(dynb, mb, tmem,
                 &g_Ah[b][s][mt * 128][0], &g_Al[b][s][mt * 128][0], KP,
                 &g_Xh[b][nt * 256][0], &g_Xl[b][nt * 256][0], KP);

    int wid = threadIdx.x >> 5, lane = threadIdx.x & 31;
    if (wid < 4) {  // warps 0-3 cover the 128 TMEM lanes (rows j)
        int j = mt * 128 + wid * 32 + lane;
        bool ok = (j < K_DIM);
        int ch0 = 64 + s * 64;
#pragma unroll 1
        for (int q = 0; q < 8; ++q) {
            __align__(16) uint32_t r[32];
            TC_LD_X32(r, tmem + q * 32);
            TC_WAIT_LD();
            if (ok) {
                int l = nt * 4 + (q >> 1), c0 = (q & 1) * 32;
                __align__(16) __half hh[32], hl[32];
#pragma unroll
                for (int i = 0; i < 32; ++i)
                    split_hl(__uint_as_float(r[i]), hh[i], hl[i]);
                uint4* dh = (uint4*)&g_hh[b][j * 64 + l][ch0 + c0];
                uint4* dl = (uint4*)&g_hl[b][j * 64 + l][ch0 + c0];
#pragma unroll
                for (int u = 0; u < 4; ++u) { dh[u] = ((uint4*)hh)[u]; dl[u] = ((uint4*)hl)[u]; }
            }
        }
    }
    __syncthreads();
    if (threadIdx.x == 0) { MBAR_INVAL(mb); MBAR_INVAL(mb + 8); }
    if (threadIdx.x < 32) TC_DEALLOC(tmem, 256);
#else
    // FFMA fallback (never runs on GB300; correctness-preserving)
    __shared__ float As[16 * 68];
    __shared__ float Bs[16 * 64];
    int t = threadIdx.x;
    int tx = t & 15, ty = t >> 4;
    int la_k = t & 15, la_j = t >> 4;
    int lb_l = t & 63, lb_k = t >> 6;
    int ch0 = 64 + s * 64;

    for (int jt = 0; jt < 2; ++jt) {
        int row0 = mt * 128 + jt * 64;
        if (row0 >= K_DIM) break;
        for (int ct = 0; ct < 4; ++ct) {
            int c = nt * 4 + ct;
            const float* X = x + (long)b * CKL + (long)c * KL;
            unsigned long long zz = pack2(0.f, 0.f);
            unsigned long long acc[4][2];
#pragma unroll
            for (int u = 0; u < 4; ++u) { acc[u][0] = zz; acc[u][1] = zz; }
            for (int k0 = 0; k0 < K_DIM; k0 += 16) {
                __syncthreads();
#pragma unroll
                for (int p = 0; p < 4; ++p) {
                    int jj = la_j + p * 16;
                    int gj = row0 + jj, gk = k0 + la_k;
                    As[la_k * 68 + jj] =
                        (gj < KP && gk < KP)
                            ? (__half2float(g_Ah[b][s][gj][gk]) +
                               __half2float(g_Al[b][s][gj][gk]))
                            : 0.f;
                }
#pragma unroll
                for (int p = 0; p < 4; ++p) {
                    int kk = lb_k + p * 4;
                    int gk = k0 + kk;
                    Bs[kk * 64 + lb_l] = (gk < K_DIM) ? X[gk * 64 + lb_l] : 0.f;
                }
                __syncthreads();
                mm_tile(As, Bs, acc, ty, tx);
            }
#pragma unroll
            for (int u = 0; u < 4; ++u) {
                int gj = row0 + ty * 4 + u;
                if (gj < K_DIM) {
                    float2 p01 = unpack2(acc[u][0]);
                    float2 p23 = unpack2(acc[u][1]);
                    float vals[4] = {p01.x, p01.y, p23.x, p23.y};
#pragma unroll
                    for (int v = 0; v < 4; ++v) {
                        int l = tx * 4 + v;
                        __half hi, lo;
                        split_hl(vals[v], hi, lo);
                        g_hh[b][gj * 64 + l][ch0 + c] = hi;
                        g_hl[b][gj * 64 + l][ch0 + c] = lo;
                    }
                }
            }
            __syncthreads();
        }
    }
#endif
}

// ---------- kernel: conv y = W @ h + bias, grid (nt=52, b=16) ------------------
__global__ __launch_bounds__(256, 1) void k_conv(const float* __restrict__ W,
                                                 const float* __restrict__ bias,
                                                 float* __restrict__ y) {
    int nt = blockIdx.x, b = blockIdx.y;
#if HAVE_TC
    extern __shared__ char dyn[];
    __shared__ uint32_t s_ctrl[1];
    __shared__ __align__(8) unsigned long long s_mb[2];

    uint32_t ctrl = smem_u32(s_ctrl), mb = smem_u32(s_mb);
    if (threadIdx.x < 32) TC_ALLOC(ctrl, 256);
    if (threadIdx.x == 0) { MBAR_INIT(mb, 1); MBAR_INIT(mb + 8, 1); }
    __syncthreads();
    uint32_t tmem;
    asm volatile("ld.shared.b32 %0, [%1];" : "=r"(tmem) : "r"(ctrl));
    uint32_t dynb = (smem_u32(dyn) + 1023u) & ~1023u;

    gemm_main<5>(dynb, mb, tmem,
                 &g_Wh[0][0], &g_Wl[0][0], CIN,
                 &g_hh[b][nt * 256][0], &g_hl[b][nt * 256][0], CIN);

    int wid = threadIdx.x >> 5, lane = threadIdx.x & 31;
    if (wid < 2) {  // TMEM lanes 0..63 = output channels
        int o = wid * 32 + lane;
        float bv = bias[o];
        float* yp = y + (long)b * CKL + (long)o * KL;
#pragma unroll 1
        for (int q = 0; q < 8; ++q) {
            __align__(16) uint32_t r[32];
            TC_LD_X32(r, tmem + q * 32);
            TC_WAIT_LD();
            int n0 = nt * 256 + q * 32;
            if (n0 < KL) {
                __align__(16) float v[32];
#pragma unroll
                for (int i = 0; i < 32; ++i) v[i] = __uint_as_float(r[i]) + bv;
                uint4* dst = (uint4*)(yp + n0);
#pragma unroll
                for (int u = 0; u < 8; ++u) dst[u] = ((uint4*)v)[u];
            }
        }
    }
    __syncthreads();
    if (threadIdx.x == 0) { MBAR_INVAL(mb); MBAR_INVAL(mb + 8); }
    if (threadIdx.x < 32) TC_DEALLOC(tmem, 256);
#else
    // FFMA fallback
    __shared__ float As[16 * 68];
    __shared__ float Bs[16 * 64];
    int t = threadIdx.x;
    int tx = t & 15, ty = t >> 4;
    int la_k = t & 15, la_j = t >> 4;
    int lb_l = t & 63, lb_k = t >> 6;

    for (int sub = 0; sub < 4; ++sub) {
        int n0 = nt * 256 + sub * 64;
        if (n0 >= KL) break;
        unsigned long long acc[4][2];
#pragma unroll
        for (int u = 0; u < 4; ++u) {
            float bv = bias[ty * 4 + u];
            acc[u][0] = pack2(bv, bv);
            acc[u][1] = pack2(bv, bv);
        }
        for (int i0 = 0; i0 < CIN; i0 += 16) {
            __syncthreads();
#pragma unroll
            for (int p = 0; p < 4; ++p) {
                int o = la_j + p * 16;
                As[la_k * 68 + o] = (o < 64) ? W[o * CIN + i0 + la_k] : 0.f;
            }
#pragma unroll
            for (int p = 0; p < 4; ++p) {
                int ii = lb_k + p * 4;
                int i = i0 + ii;
                int n = n0 + lb_l;
                Bs[ii * 64 + lb_l] = __half2float(g_hh[b][n][i]) +
                                     __half2float(g_hl[b][n][i]);
            }
            __syncthreads();
            mm_tile(As, Bs, acc, ty, tx);
        }
#pragma unroll
        for (int u = 0; u < 4; ++u) {
            int o = ty * 4 + u;
            if (o < 64) {
                float2 p01 = unpack2(acc[u][0]);
                float2 p23 = unpack2(acc[u][1]);
                float4 ov = make_float4(p01.x, p01.y, p23.x, p23.y);
                *(float4*)(y + (long)b * CKL + (long)o * KL + n0 + tx * 4) = ov;
            }
        }
        __syncthreads();
    }
#endif
}

extern "C" void kernel_launch(void* const* d_in, const int* in_sizes, int n_in,
                              void* d_out, int out_size) {
    const float* x    = (const float*)d_in[0];   // (16, 64, 13248)
    const float* a0   = (const float*)d_in[1];   // (16, 207, 207)
    const float* a1   = (const float*)d_in[2];   // (16, 207, 207)
    const float* W    = (const float*)d_in[3];   // (64, 320)
    const float* bias = (const float*)d_in[4];   // (64,)
    float* y = (float*)d_out;                    // (16, 64, 13248)

    cudaFuncSetAttribute(k_sq, cudaFuncAttributeMaxDynamicSharedMemorySize,
                         2 * STG + 1024);
    cudaFuncSetAttribute(k_diffuse, cudaFuncAttributeMaxDynamicSharedMemorySize,
                         2 * STG + 1024);
    cudaFuncSetAttribute(k_conv, cudaFuncAttributeMaxDynamicSharedMemorySize,
                         2 * STG + 1024);
    cudaFuncSetAttribute(prep_X, cudaFuncAttributeMaxDynamicSharedMemorySize,
                         207 * 68 * 4);

    dim3 blk(256);
    prep_A<<<dim3(256, 32), blk>>>(a0, a1);
    prep_AT<<<dim3(4, 4, 32), blk>>>(a0, a1);
    k_sq<<<dim3(1, 2, 32), blk, 2 * STG + 1024>>>();
    prep_X<<<dim3(64, 16), dim3(512), 207 * 68 * 4>>>(x);
    prep_xh<<<dim3(207, 16), blk>>>(x);
    prep_W<<<dim3(160), blk>>>(W);
    k_diffuse<<<dim3(8, 16, 16), blk, 2 * STG + 1024>>>(x);
    k_conv<<<dim3(52, 16), blk, 2 * STG + 1024>>>(W, bias, y);
}

// round 10
// speedup vs baseline: 1.0556x; 1.0017x over previous
#include <cuda_runtime.h>
#include <cuda_fp16.h>
#include <cstdint>

#define B_DIM 16
#define C_DIM 64
#define K_DIM 207
#define L_DIM 64
#define KL 13248          // K_DIM * L_DIM
#define CKL (C_DIM * KL)  // 847872
#define KK2 42849         // K_DIM * K_DIM
#define CLDIM 4096        // C_DIM * L_DIM
#define KP 256            // padded K / M for tensor path
#define CIN 320           // conv input channels
#define NH 13312          // padded (j,l) rows = 52*256

// Does this device-compilation pass support tcgen05? ('a'-arch targets only)
#if defined(__CUDA_ARCH_FEAT_SM103_ALL) || defined(__CUDA_ARCH_FEAT_SM100_ALL) || \
    defined(__CUDA_ARCH_FEAT_SM101_ALL)
#define HAVE_TC 1
#else
#define HAVE_TC 0
#endif

// Scratch (device globals: allocation-free per harness rules; zero-initialized)
__device__ __half g_Ah[B_DIM][4][KP][KP];             // A hi; s:0=A0,1=A0^2,2=A1,3=A1^2
__device__ __half g_Al[B_DIM][4][KP][KP];             // A lo
__device__ __half g_ATh[B_DIM][2][KP][KP];            // A^T hi (for squaring), s2:0=A0,1=A1
__device__ __half g_ATl[B_DIM][2][KP][KP];            // A^T lo
__device__ __half g_Xh[B_DIM][CLDIM][KP];             // X^T hi: [b][l*64+c][k]
__device__ __half g_Xl[B_DIM][CLDIM][KP];             // X^T lo
__device__ __half g_hh[B_DIM][NH][CIN];               // h=[x;G] hi: [b][j*64+l][ch]
__device__ __half g_hl[B_DIM][NH][CIN];               // h lo
__device__ __half g_Wh[128][CIN];                     // W hi, rows 64..127 zero
__device__ __half g_Wl[128][CIN];                     // W lo

// ---------- packed f32x2 helpers ----------
__device__ __forceinline__ unsigned long long pack2(float lo, float hi) {
    unsigned long long r;
    asm("mov.b64 %0, {%1, %2};" : "=l"(r) : "f"(lo), "f"(hi));
    return r;
}
__device__ __forceinline__ void fma2(unsigned long long& d, unsigned long long a,
                                     unsigned long long b) {
    asm("fma.rn.f32x2 %0, %1, %2, %0;" : "+l"(d) : "l"(a), "l"(b));
}
__device__ __forceinline__ float2 unpack2(unsigned long long v) {
    float2 f;
    asm("mov.b64 {%0, %1}, %2;" : "=f"(f.x), "=f"(f.y) : "l"(v));
    return f;
}
__device__ __forceinline__ void split_hl(float v, __half& hi, __half& lo) {
    hi = __float2half_rn(v);
    lo = __float2half_rn(v - __half2float(hi));
}

// ---------- FFMA 64x64 microkernel (fallback paths only) ----------
__device__ __forceinline__ void mm_tile(const float* __restrict__ As,
                                        const float* __restrict__ Bs,
                                        unsigned long long (&acc)[4][2],
                                        int ty, int tx) {
#pragma unroll
    for (int kk = 0; kk < 16; ++kk) {
        float4 av = *(const float4*)(As + kk * 68 + ty * 4);
        float4 bv = *(const float4*)(Bs + kk * 64 + tx * 4);
        unsigned long long b01 = pack2(bv.x, bv.y);
        unsigned long long b23 = pack2(bv.z, bv.w);
        unsigned long long a;
        a = pack2(av.x, av.x); fma2(acc[0][0], a, b01); fma2(acc[0][1], a, b23);
        a = pack2(av.y, av.y); fma2(acc[1][0], a, b01); fma2(acc[1][1], a, b23);
        a = pack2(av.z, av.z); fma2(acc[2][0], a, b01); fma2(acc[2][1], a, b23);
        a = pack2(av.w, av.w); fma2(acc[3][0], a, b01); fma2(acc[3][1], a, b23);
    }
}

// ---------- prep: A (s=0,2) -> fp16 hi/lo, zero-padded; grid (256, 32) ----------
__global__ __launch_bounds__(256) void prep_A(const float* __restrict__ a0,
                                              const float* __restrict__ a1) {
    int j = blockIdx.x;            // 0..255
    int bz = blockIdx.y;           // b*2+s2
    int b = bz >> 1, s2 = bz & 1;
    int k = threadIdx.x;
    const float* src = (s2 ? a1 : a0) + b * KK2;
    float v = (j < K_DIM && k < K_DIM) ? src[j * K_DIM + k] : 0.f;
    __half hi, lo;
    split_hl(v, hi, lo);
    g_Ah[b][2 * s2][j][k] = hi;
    g_Al[b][2 * s2][j][k] = lo;
}

// ---------- prep: A^T (s2=0,1) via smem transpose; grid (4, 4, 32) ----------
__global__ __launch_bounds__(256) void prep_AT(const float* __restrict__ a0,
                                               const float* __restrict__ a1) {
    __shared__ float s[64][65];
    int kt = blockIdx.x, jt = blockIdx.y, bz = blockIdx.z;
    int b = bz >> 1, s2 = bz & 1;
    const float* src = (s2 ? a1 : a0) + b * KK2;
    int t = threadIdx.x;
    int col = t & 63, row4 = t >> 6;
#pragma unroll
    for (int it = 0; it < 16; ++it) {
        int lj = it * 4 + row4;
        int j = jt * 64 + lj, k = kt * 64 + col;
        s[lj][col] = (j < K_DIM && k < K_DIM) ? src[j * K_DIM + k] : 0.f;
    }
    __syncthreads();
#pragma unroll
    for (int it = 0; it < 16; ++it) {
        int r = it * 4 + row4;          // local k
        float v = s[col][r];            // AT[k][j] = A[j][k]
        __half hi, lo;
        split_hl(v, hi, lo);
        g_ATh[b][s2][kt * 64 + r][jt * 64 + col] = hi;
        g_ATl[b][s2][kt * 64 + r][jt * 64 + col] = lo;
    }
}

// ---------- prep: transpose X to [b][l*64+c][k] fp16 hi/lo; 512 thr, float4 ----
__global__ __launch_bounds__(512) void prep_X(const float* __restrict__ x) {
    extern __shared__ float s_x[];     // [207][68]
    int c = blockIdx.x, b = blockIdx.y;
    const float* xp = x + (long)b * CKL + (long)c * KL;
    int t = threadIdx.x;
    // 13248 floats = 3312 float4; layout [k][l], row pad 68 (272B, 16B-aligned)
#pragma unroll
    for (int it = 0; it < 7; ++it) {
        int idx = it * 512 + t;
        if (idx < 3312) {
            float4 v = ((const float4*)xp)[idx];
            int k = idx >> 4, l4 = (idx & 15) * 4;
            *(float4*)&s_x[k * 68 + l4] = v;
        }
    }
    __syncthreads();
    int kq = t >> 6, l = t & 63;       // kq 0..7, each handles 32 k
    __align__(16) __half hh[32], hl[32];
#pragma unroll
    for (int i = 0; i < 32; ++i) {
        int k = kq * 32 + i;
        float v = (k < K_DIM) ? s_x[k * 68 + l] : 0.f;
        split_hl(v, hh[i], hl[i]);
    }
    uint4* dh = (uint4*)&g_Xh[b][l * 64 + c][kq * 32];
    uint4* dl = (uint4*)&g_Xl[b][l * 64 + c][kq * 32];
#pragma unroll
    for (int i = 0; i < 4; ++i) { dh[i] = ((uint4*)hh)[i]; dl[i] = ((uint4*)hl)[i]; }
}

// ---------- prep: x -> channels [0,64) of g_h (hi/lo), grid (207, 16) ----------
__global__ __launch_bounds__(256) void prep_xh(const float* __restrict__ x) {
    __shared__ float sx[64][68];
    int j = blockIdx.x, b = blockIdx.y;
    int t = threadIdx.x;
    const float* xp = x + (long)b * CKL + j * 64;
#pragma unroll
    for (int it = 0; it < 4; ++it) {
        int idx = it * 256 + t;        // float4 index within [c][l]
        int c = idx >> 4, l4 = (idx & 15) * 4;
        float4 v = *(const float4*)(xp + (long)c * KL + l4);
        *(float4*)&sx[c][l4] = v;
    }
    __syncthreads();
#pragma unroll
    for (int it = 0; it < 2; ++it) {
        int idx = it * 256 + t;
        int l = idx >> 3, q = idx & 7;       // 8 channels per thread
        __align__(16) __half hh[8], hl[8];
#pragma unroll
        for (int i = 0; i < 8; ++i) split_hl(sx[q * 8 + i][l], hh[i], hl[i]);
        *((uint4*)&g_hh[b][j * 64 + l][0] + q) = *(uint4*)hh;
        *((uint4*)&g_hl[b][j * 64 + l][0] + q) = *(uint4*)hl;
    }
}

// ---------- prep: W -> padded fp16 hi/lo, grid (160) ----------
__global__ __launch_bounds__(256) void prep_W(const float* __restrict__ W) {
    int idx = blockIdx.x * 256 + threadIdx.x;   // 0..40959
    int o = idx / CIN, i = idx - o * CIN;
    float v = (o < 64) ? W[o * CIN + i] : 0.f;
    __half hi, lo;
    split_hl(v, hi, lo);
    g_Wh[o][i] = hi;
    g_Wl[o][i] = lo;
}

// ---------------- tcgen05 plumbing (expanded only on 'a'-arch pass) ------------
__device__ __forceinline__ uint32_t smem_u32(const void* p) {
    uint32_t a;
    asm("{ .reg .u64 t; cvta.to.shared.u64 t, %1; cvt.u32.u64 %0, t; }" : "=r"(a) : "l"(p));
    return a;
}
#if HAVE_TC
__device__ __forceinline__ uint32_t elect1() {
    uint32_t p;
    asm volatile("{\n\t.reg .pred p;\n\telect.sync _|p, 0xFFFFFFFF;\n\tselp.b32 %0, 1, 0, p;\n\t}"
                 : "=r"(p));
    return p;
}
static constexpr uint64_t DESC_SW128 =
    (uint64_t(2) << 61) | (uint64_t(1) << 46) | (uint64_t(64) << 32) | (uint64_t(1) << 16);
__device__ __forceinline__ uint64_t mk_desc(uint32_t a) {
    return DESC_SW128 | ((uint64_t)(a >> 4) & 0x3FFF);
}
#define MBAR_INIT(a, c) asm volatile("mbarrier.init.shared.b64 [%0], %1;" :: "r"(a), "r"(c) : "memory")
#define MBAR_INVAL(a)   asm volatile("mbarrier.inval.shared.b64 [%0];" :: "r"(a) : "memory")
#define MBAR_WAIT(a, par) do {                                                     \
    uint32_t _m = (a), _p = (par), _d;                                             \
    asm volatile("{\n\t.reg .pred p;\n\t"                                          \
        "mbarrier.try_wait.parity.acquire.cta.shared::cta.b64 p, [%1], %2;\n\t"    \
        "selp.b32 %0, 1, 0, p;\n\t}" : "=r"(_d) : "r"(_m), "r"(_p) : "memory");    \
    if (!_d) {                                                                     \
        asm volatile("{\n\t.reg .pred P1;\n\t"                                     \
            "WL_%=:\n\t"                                                           \
            "mbarrier.try_wait.parity.acquire.cta.shared::cta.b64 P1, [%0], %1, 0x989680;\n\t" \
            "@P1 bra.uni WD_%=;\n\tbra.uni WL_%=;\n\tWD_%=:\n\t}"                  \
            :: "r"(_m), "r"(_p) : "memory");                                       \
    }                                                                              \
} while (0)
#define TC_ALLOC(sm, n) \
    asm volatile("tcgen05.alloc.cta_group::1.sync.aligned.shared::cta.b32 [%0], %1;" :: "r"(sm), "r"(n) : "memory")
#define TC_DEALLOC(t, n) \
    asm volatile("tcgen05.dealloc.cta_group::1.sync.aligned.b32 %0, %1;" :: "r"(t), "r"(n))
#define TC_COMMIT(mb) \
    asm volatile("tcgen05.commit.cta_group::1.mbarrier::arrive::one.shared::cluster.b64 [%0];" :: "r"(mb) : "memory")
#define TC_WAIT_LD()     asm volatile("tcgen05.wait::ld.sync.aligned;" ::: "memory")
#define TC_FENCE_AFTER() asm volatile("tcgen05.fence::after_thread_sync;" ::: "memory")

#define TC_LD_X32(r, ta)                                                            \
    asm volatile("tcgen05.ld.sync.aligned.32x32b.x32.b32 "                          \
        "{%0, %1, %2, %3, %4, %5, %6, %7, %8, %9, %10, %11, %12, %13, %14, %15, "   \
        " %16, %17, %18, %19, %20, %21, %22, %23, %24, %25, %26, %27, %28, %29, %30, %31}, [%32];" \
        : "=r"((r)[0]), "=r"((r)[1]), "=r"((r)[2]), "=r"((r)[3]),                   \
          "=r"((r)[4]), "=r"((r)[5]), "=r"((r)[6]), "=r"((r)[7]),                   \
          "=r"((r)[8]), "=r"((r)[9]), "=r"((r)[10]), "=r"((r)[11]),                 \
          "=r"((r)[12]), "=r"((r)[13]), "=r"((r)[14]), "=r"((r)[15]),               \
          "=r"((r)[16]), "=r"((r)[17]), "=r"((r)[18]), "=r"((r)[19]),               \
          "=r"((r)[20]), "=r"((r)[21]), "=r"((r)[22]), "=r"((r)[23]),               \
          "=r"((r)[24]), "=r"((r)[25]), "=r"((r)[26]), "=r"((r)[27]),               \
          "=r"((r)[28]), "=r"((r)[29]), "=r"((r)[30]), "=r"((r)[31])                \
        : "r"(ta))

// f16 SS MMA, cg1, M=128, N=64 (field layout verified vs bf16 0x8080490)
#define IDESC_F16 0x8100010u
__device__ __forceinline__ void mma16(uint32_t d, uint64_t ad, uint64_t bd, uint32_t en) {
    asm volatile("{\n\t.reg .pred p;\n\tsetp.ne.u32 p, %3, 0;\n\t"
        "tcgen05.mma.cta_group::1.kind::f16 [%0], %1, %2, %4, {%5, %5, %5, %5}, p;\n\t}"
        :: "r"(d), "l"(ad), "l"(bd), "r"(en), "r"(IDESC_F16), "r"(0u) : "memory");
}

// async-copy R rows x 128B from global into SW128 smem tile
template <int R>
__device__ __forceinline__ void ld_tile(uint32_t dst, const __half* src, int stride_h) {
    const char* s8 = (const char*)src;
    long sb = (long)stride_h * 2;
#pragma unroll
    for (int u = 0; u < (R * 8) / 256; ++u) {
        int idx = u * 256 + threadIdx.x;
        int r = idx >> 3, q = idx & 7;
        const void* sp = s8 + (long)r * sb + q * 16;
        uint32_t off = r * 128 + q * 16;
        uint32_t d = dst + (off ^ ((off >> 3) & 0x70));
        asm volatile("cp.async.cg.shared.global [%0], [%1], 16;" :: "r"(d), "l"(sp));
    }
}

__device__ __forceinline__ void load_chunk(uint32_t sb, int ck,
                                           const __half* Ah, const __half* Al, int astr,
                                           const __half* Bh, const __half* Bl, int bstr) {
    ld_tile<128>(sb,         Ah + ck * 64, astr);
    ld_tile<128>(sb + 16384, Al + ck * 64, astr);
    ld_tile<256>(sb + 32768, Bh + ck * 64, bstr);
    ld_tile<256>(sb + 65536, Bl + ck * 64, bstr);
    asm volatile("cp.async.commit_group;" ::: "memory");
}

// double-buffered 3-term mainloop; D = 128x256 fp32 in TMEM cols [0,256)
template <int NC>
__device__ __forceinline__ void gemm_main(uint32_t dynb, uint32_t mb, uint32_t tmem,
                                          const __half* Ah, const __half* Al, int astr,
                                          const __half* Bh, const __half* Bl, int bstr) {
    load_chunk(dynb, 0, Ah, Al, astr, Bh, Bl, bstr);
    int p0 = 0, p1 = 0;
#pragma unroll 1
    for (int i = 0; i < NC; ++i) {
        int q = i & 1;
        asm volatile("cp.async.wait_group 0;" ::: "memory");
        asm volatile("fence.proxy.async.shared::cta;" ::: "memory");
        __syncthreads();
        if (threadIdx.x < 32 && elect1()) {
            uint32_t sb = dynb + q * 98304;
            uint64_t dAh = mk_desc(sb), dAl = mk_desc(sb + 16384);
            uint64_t dBh = mk_desc(sb + 32768), dBl = mk_desc(sb + 65536);
#pragma unroll
            for (int t = 0; t < 3; ++t) {          // Ah*Bh, Ah*Bl, Al*Bh
                uint64_t ad = (t == 2) ? dAl : dAh;
                uint64_t bd = (t == 1) ? dBl : dBh;
#pragma unroll
                for (int ks = 0; ks < 4; ++ks)
#pragma unroll
                    for (int ng = 0; ng < 4; ++ng) {
                        uint32_t en = !(i == 0 && t == 0 && ks == 0);
                        mma16(tmem + ng * 64, ad + ks * 2, bd + ng * 512 + ks * 2, en);
                    }
            }
            TC_COMMIT(mb + q * 8);
        }
        if (i + 1 < NC) {
            int q2 = (i + 1) & 1;
            if (i >= 1) {
                if (q2 == 0) { MBAR_WAIT(mb, p0); p0 ^= 1; }
                else         { MBAR_WAIT(mb + 8, p1); p1 ^= 1; }
            }
            load_chunk(dynb + q2 * 98304, i + 1, Ah, Al, astr, Bh, Bl, bstr);
        }
    }
    MBAR_WAIT(mb, p0);
    MBAR_WAIT(mb + 8, p1);
    TC_FENCE_AFTER();
}
#endif  // HAVE_TC

#define STG 98304  // stage: Ah 16K | Al 16K | Bh 32K | Bl 32K

// ---------- kernel: A^2 on tensor cores; grid (1, mt=2, b*2+s2=32) -------------
__global__ __launch_bounds__(256, 1) void k_sq() {
    int mt = blockIdx.y, bz = blockIdx.z;
    int b = bz >> 1, s2 = bz & 1;
#if HAVE_TC
    extern __shared__ char dyn[];
    __shared__ uint32_t s_ctrl[1];
    __shared__ __align__(8) unsigned long long s_mb[2];

    uint32_t ctrl = smem_u32(s_ctrl), mb = smem_u32(s_mb);
    if (threadIdx.x < 32) TC_ALLOC(ctrl, 256);
    if (threadIdx.x == 0) { MBAR_INIT(mb, 1); MBAR_INIT(mb + 8, 1); }
    __syncthreads();
    uint32_t tmem;
    asm volatile("ld.shared.b32 %0, [%1];" : "=r"(tmem) : "r"(ctrl));
    uint32_t dynb = (smem_u32(dyn) + 1023u) & ~1023u;

    gemm_main<4>(dynb, mb, tmem,
                 &g_Ah[b][2 * s2][mt * 128][0], &g_Al[b][2 * s2][mt * 128][0], KP,
                 &g_ATh[b][s2][0][0], &g_ATl[b][s2][0][0], KP);

    int wid = threadIdx.x >> 5, lane = threadIdx.x & 31;
    if (wid < 4) {
        int j = mt * 128 + wid * 32 + lane;
#pragma unroll 1
        for (int q = 0; q < 8; ++q) {
            __align__(16) uint32_t r[32];
            TC_LD_X32(r, tmem + q * 32);
            TC_WAIT_LD();
            __align__(16) __half hh[32], hl[32];
#pragma unroll
            for (int i = 0; i < 32; ++i) split_hl(__uint_as_float(r[i]), hh[i], hl[i]);
            uint4* dh = (uint4*)&g_Ah[b][2 * s2 + 1][j][q * 32];
            uint4* dl = (uint4*)&g_Al[b][2 * s2 + 1][j][q * 32];
#pragma unroll
            for (int u = 0; u < 4; ++u) { dh[u] = ((uint4*)hh)[u]; dl[u] = ((uint4*)hl)[u]; }
        }
    }
    __syncthreads();
    if (threadIdx.x == 0) { MBAR_INVAL(mb); MBAR_INVAL(mb + 8); }
    if (threadIdx.x < 32) TC_DEALLOC(tmem, 256);
#else
    // FFMA fallback: A^2 tile rows [mt*128,+128) x cols [0,256)
    __shared__ float As[16 * 68];
    __shared__ float Bs[16 * 64];
    int t = threadIdx.x;
    int tx = t & 15, ty = t >> 4;
    int la_k = t & 15, la_j = t >> 4;
    int lb_l = t & 63, lb_k = t >> 6;

    for (int jt = 0; jt < 2; ++jt) {
        int row0 = mt * 128 + jt * 64;
        for (int ct = 0; ct < 4; ++ct) {
            int col0 = ct * 64;
            unsigned long long zz = pack2(0.f, 0.f);
            unsigned long long acc[4][2];
#pragma unroll
            for (int u = 0; u < 4; ++u) { acc[u][0] = zz; acc[u][1] = zz; }
            for (int k0 = 0; k0 < KP; k0 += 16) {
                __syncthreads();
#pragma unroll
                for (int p = 0; p < 4; ++p) {
                    int jj = la_j + p * 16;
                    As[la_k * 68 + jj] =
                        __half2float(g_Ah[b][2 * s2][row0 + jj][k0 + la_k]) +
                        __half2float(g_Al[b][2 * s2][row0 + jj][k0 + la_k]);
                }
#pragma unroll
                for (int p = 0; p < 4; ++p) {
                    int kk = lb_k + p * 4;
                    Bs[kk * 64 + lb_l] =
                        __half2float(g_ATh[b][s2][k0 + kk][col0 + lb_l]) +
                        __half2float(g_ATl[b][s2][k0 + kk][col0 + lb_l]);
                }
                __syncthreads();
                mm_tile(As, Bs, acc, ty, tx);
            }
#pragma unroll
            for (int u = 0; u < 4; ++u) {
                int gj = row0 + ty * 4 + u;
                float2 p01 = unpack2(acc[u][0]);
                float2 p23 = unpack2(acc[u][1]);
                float vals[4] = {p01.x, p01.y, p23.x, p23.y};
#pragma unroll
                for (int v = 0; v < 4; ++v) {
                    __half hi, lo;
                    split_hl(vals[v], hi, lo);
                    g_Ah[b][2 * s2 + 1][gj][col0 + tx * 4 + v] = hi;
                    g_Al[b][2 * s2 + 1][gj][col0 + tx * 4 + v] = lo;
                }
            }
            __syncthreads();
        }
    }
#endif
}

// ---------- kernel: diffusion, grid (smt=8, nt=16, b=16) -----------------------
// blockIdx.x = s*2+mt so the 8 CTAs sharing one B tile are launch-adjacent (L2 reuse)
__global__ __launch_bounds__(256, 1) void k_diffuse(const float* __restrict__ x) {
    int smt = blockIdx.x, nt = blockIdx.y, b = blockIdx.z;
    int s = smt >> 1, mt = smt & 1;
#if HAVE_TC
    extern __shared__ char dyn[];
    __shared__ uint32_t s_ctrl[1];
    __shared__ __align__(8) unsigned long long s_mb[2];

    uint32_t ctrl = smem_u32(s_ctrl), mb = smem_u32(s_mb);
    if (threadIdx.x < 32) TC_ALLOC(ctrl, 256);
    if (threadIdx.x == 0) { MBAR_INIT(mb, 1); MBAR_INIT(mb + 8, 1); }
    __syncthreads();
    uint32_t tmem;
    asm volatile("ld.shared.b32 %0, [%1];" : "=r"(tmem) : "r"(ctrl));
    uint32_t dynb = (smem_u32(dyn) + 1023u) & ~1023u;

    gemm_main<4>(dynb, mb, tmem,
                 &g_Ah[b][s][mt * 128][0], &g_Al[b][s][mt * 128][0], KP,
                 &g_Xh[b][nt * 256][0], &g_Xl[b][nt * 256][0], KP);

    int wid = threadIdx.x >> 5, lane = threadIdx.x & 31;
    if (wid < 4) {  // warps 0-3 cover the 128 TMEM lanes (rows j)
        int j = mt * 128 + wid * 32 + lane;
        bool ok = (j < K_DIM);
        int ch0 = 64 + s * 64;
#pragma unroll 1
        for (int q = 0; q < 8; ++q) {
            __align__(16) uint32_t r[32];
            TC_LD_X32(r, tmem + q * 32);
            TC_WAIT_LD();
            if (ok) {
                int l = nt * 4 + (q >> 1), c0 = (q & 1) * 32;
                __align__(16) __half hh[32], hl[32];
#pragma unroll
                for (int i = 0; i < 32; ++i)
                    split_hl(__uint_as_float(r[i]), hh[i], hl[i]);
                uint4* dh = (uint4*)&g_hh[b][j * 64 + l][ch0 + c0];
                uint4* dl = (uint4*)&g_hl[b][j * 64 + l][ch0 + c0];
#pragma unroll
                for (int u = 0; u < 4; ++u) { dh[u] = ((uint4*)hh)[u]; dl[u] = ((uint4*)hl)[u]; }
            }
        }
    }
    __syncthreads();
    if (threadIdx.x == 0) { MBAR_INVAL(mb); MBAR_INVAL(mb + 8); }
    if (threadIdx.x < 32) TC_DEALLOC(tmem, 256);
#else
    // FFMA fallback (never runs on GB300; correctness-preserving)
    __shared__ float As[16 * 68];
    __shared__ float Bs[16 * 64];
    int t = threadIdx.x;
    int tx = t & 15, ty = t >> 4;
    int la_k = t & 15, la_j = t >> 4;
    int lb_l = t & 63, lb_k = t >> 6;
    int ch0 = 64 + s * 64;

    for (int jt = 0; jt < 2; ++jt) {
        int row0 = mt * 128 + jt * 64;
        if (row0 >= K_DIM) break;
        for (int ct = 0; ct < 4; ++ct) {
            int c = nt * 4 + ct;
            const float* X = x + (long)b * CKL + (long)c * KL;
            unsigned long long zz = pack2(0.f, 0.f);
            unsigned long long acc[4][2];
#pragma unroll
            for (int u = 0; u < 4; ++u) { acc[u][0] = zz; acc[u][1] = zz; }
            for (int k0 = 0; k0 < K_DIM; k0 += 16) {
                __syncthreads();
#pragma unroll
                for (int p = 0; p < 4; ++p) {
                    int jj = la_j + p * 16;
                    int gj = row0 + jj, gk = k0 + la_k;
                    As[la_k * 68 + jj] =
                        (gj < KP && gk < KP)
                            ? (__half2float(g_Ah[b][s][gj][gk]) +
                               __half2float(g_Al[b][s][gj][gk]))
                            : 0.f;
                }
#pragma unroll
                for (int p = 0; p < 4; ++p) {
                    int kk = lb_k + p * 4;
                    int gk = k0 + kk;
                    Bs[kk * 64 + lb_l] = (gk < K_DIM) ? X[gk * 64 + lb_l] : 0.f;
                }
                __syncthreads();
                mm_tile(As, Bs, acc, ty, tx);
            }
#pragma unroll
            for (int u = 0; u < 4; ++u) {
                int gj = row0 + ty * 4 + u;
                if (gj < K_DIM) {
                    float2 p01 = unpack2(acc[u][0]);
                    float2 p23 = unpack2(acc[u][1]);
                    float vals[4] = {p01.x, p01.y, p23.x, p23.y};
#pragma unroll
                    for (int v = 0; v < 4; ++v) {
                        int l = tx * 4 + v;
                        __half hi, lo;
                        split_hl(vals[v], hi, lo);
                        g_hh[b][gj * 64 + l][ch0 + c] = hi;
                        g_hl[b][gj * 64 + l][ch0 + c] = lo;
                    }
                }
            }
            __syncthreads();
        }
    }
#endif
}

// ---------- kernel: conv y = W @ h + bias, grid (nt=52, b=16) ------------------
__global__ __launch_bounds__(256, 1) void k_conv(const float* __restrict__ W,
                                                 const float* __restrict__ bias,
                                                 float* __restrict__ y) {
    int nt = blockIdx.x, b = blockIdx.y;
#if HAVE_TC
    extern __shared__ char dyn[];
    __shared__ uint32_t s_ctrl[1];
    __shared__ __align__(8) unsigned long long s_mb[2];

    uint32_t ctrl = smem_u32(s_ctrl), mb = smem_u32(s_mb);
    if (threadIdx.x < 32) TC_ALLOC(ctrl, 256);
    if (threadIdx.x == 0) { MBAR_INIT(mb, 1); MBAR_INIT(mb + 8, 1); }
    __syncthreads();
    uint32_t tmem;
    asm volatile("ld.shared.b32 %0, [%1];" : "=r"(tmem) : "r"(ctrl));
    uint32_t dynb = (smem_u32(dyn) + 1023u) & ~1023u;

    gemm_main<5>(dynb, mb, tmem,
                 &g_Wh[0][0], &g_Wl[0][0], CIN,
                 &g_hh[b][nt * 256][0], &g_hl[b][nt * 256][0], CIN);

    int wid = threadIdx.x >> 5, lane = threadIdx.x & 31;
    if (wid < 2) {  // TMEM lanes 0..63 = output channels
        int o = wid * 32 + lane;
        float bv = bias[o];
        float* yp = y + (long)b * CKL + (long)o * KL;
#pragma unroll 1
        for (int q = 0; q < 8; ++q) {
            __align__(16) uint32_t r[32];
            TC_LD_X32(r, tmem + q * 32);
            TC_WAIT_LD();
            int n0 = nt * 256 + q * 32;
            if (n0 < KL) {
                __align__(16) float v[32];
#pragma unroll
                for (int i = 0; i < 32; ++i) v[i] = __uint_as_float(r[i]) + bv;
                uint4* dst = (uint4*)(yp + n0);
#pragma unroll
                for (int u = 0; u < 8; ++u) dst[u] = ((uint4*)v)[u];
            }
        }
    }
    __syncthreads();
    if (threadIdx.x == 0) { MBAR_INVAL(mb); MBAR_INVAL(mb + 8); }
    if (threadIdx.x < 32) TC_DEALLOC(tmem, 256);
#else
    // FFMA fallback
    __shared__ float As[16 * 68];
    __shared__ float Bs[16 * 64];
    int t = threadIdx.x;
    int tx = t & 15, ty = t >> 4;
    int la_k = t & 15, la_j = t >> 4;
    int lb_l = t & 63, lb_k = t >> 6;

    for (int sub = 0; sub < 4; ++sub) {
        int n0 = nt * 256 + sub * 64;
        if (n0 >= KL) break;
        unsigned long long acc[4][2];
#pragma unroll
        for (int u = 0; u < 4; ++u) {
            float bv = bias[ty * 4 + u];
            acc[u][0] = pack2(bv, bv);
            acc[u][1] = pack2(bv, bv);
        }
        for (int i0 = 0; i0 < CIN; i0 += 16) {
            __syncthreads();
#pragma unroll
            for (int p = 0; p < 4; ++p) {
                int o = la_j + p * 16;
                As[la_k * 68 + o] = (o < 64) ? W[o * CIN + i0 + la_k] : 0.f;
            }
#pragma unroll
            for (int p = 0; p < 4; ++p) {
                int ii = lb_k + p * 4;
                int i = i0 + ii;
                int n = n0 + lb_l;
                Bs[ii * 64 + lb_l] = __half2float(g_hh[b][n][i]) +
                                     __half2float(g_hl[b][n][i]);
            }
            __syncthreads();
            mm_tile(As, Bs, acc, ty, tx);
        }
#pragma unroll
        for (int u = 0; u < 4; ++u) {
            int o = ty * 4 + u;
            if (o < 64) {
                float2 p01 = unpack2(acc[u][0]);
                float2 p23 = unpack2(acc[u][1]);
                float4 ov = make_float4(p01.x, p01.y, p23.x, p23.y);
                *(float4*)(y + (long)b * CKL + (long)o * KL + n0 + tx * 4) = ov;
            }
        }
        __syncthreads();
    }
#endif
}

extern "C" void kernel_launch(void* const* d_in, const int* in_sizes, int n_in,
                              void* d_out, int out_size) {
    const float* x    = (const float*)d_in[0];   // (16, 64, 13248)
    const float* a0   = (const float*)d_in[1];   // (16, 207, 207)
    const float* a1   = (const float*)d_in[2];   // (16, 207, 207)
    const float* W    = (const float*)d_in[3];   // (64, 320)
    const float* bias = (const float*)d_in[4];   // (64,)
    float* y = (float*)d_out;                    // (16, 64, 13248)

    cudaFuncSetAttribute(k_sq, cudaFuncAttributeMaxDynamicSharedMemorySize,
                         2 * STG + 1024);
    cudaFuncSetAttribute(k_diffuse, cudaFuncAttributeMaxDynamicSharedMemorySize,
                         2 * STG + 1024);
    cudaFuncSetAttribute(k_conv, cudaFuncAttributeMaxDynamicSharedMemorySize,
                         2 * STG + 1024);
    cudaFuncSetAttribute(prep_X, cudaFuncAttributeMaxDynamicSharedMemorySize,
                         207 * 68 * 4);

    dim3 blk(256);
    prep_A<<<dim3(256, 32), blk>>>(a0, a1);
    prep_AT<<<dim3(4, 4, 32), blk>>>(a0, a1);
    k_sq<<<dim3(1, 2, 32), blk, 2 * STG + 1024>>>();
    prep_X<<<dim3(64, 16), dim3(512), 207 * 68 * 4>>>(x);
    prep_xh<<<dim3(207, 16), blk>>>(x);
    prep_W<<<dim3(160), blk>>>(W);
    k_diffuse<<<dim3(8, 16, 16), blk, 2 * STG + 1024>>>(x);
    k_conv<<<dim3(52, 16), blk, 2 * STG + 1024>>>(W, bias, y);
}

// round 13
// speedup vs baseline: 1.4670x; 1.3897x over previous
#include <cuda_runtime.h>
#include <cuda_fp16.h>
#include <cstdint>

#define B_DIM 16
#define C_DIM 64
#define K_DIM 207
#define L_DIM 64
#define KL 13248          // K_DIM * L_DIM
#define CKL (C_DIM * KL)  // 847872
#define KK2 42849         // K_DIM * K_DIM
#define CLDIM 4096        // C_DIM * L_DIM
#define KP 256            // padded K / M for tensor path
#define CIN 320           // conv input channels
#define NH 13312          // padded (j,l) rows = 52*256

// stage layout: Ah 16K | Al 16K | B 32K = 64KB  (host + device both need this)
#define STG 65536

// Does this device-compilation pass support tcgen05? ('a'-arch targets only)
#if defined(__CUDA_ARCH_FEAT_SM103_ALL) || defined(__CUDA_ARCH_FEAT_SM100_ALL) || \
    defined(__CUDA_ARCH_FEAT_SM101_ALL)
#define HAVE_TC 1
#else
#define HAVE_TC 0
#endif

// Scratch (device globals: allocation-free per harness rules; zero-initialized)
// A operands keep hi/lo (exact); B operands are single fp16 (rel err ~1.4e-4/stage).
__device__ __half g_Ah[B_DIM][4][KP][KP];             // A hi; s:0=A0,1=A0^2,2=A1,3=A1^2
__device__ __half g_Al[B_DIM][4][KP][KP];             // A lo
__device__ __half g_ATh[B_DIM][2][KP][KP];            // A^T fp16 (B operand of squaring)
__device__ __half g_Xh[B_DIM][CLDIM][KP];             // X^T fp16: [b][l*64+c][k]
__device__ __half g_hh[B_DIM][NH][CIN];               // h=[x;G] fp16: [b][j*64+l][ch]
__device__ __half g_Wh[128][CIN];                     // W hi, rows 64..127 zero
__device__ __half g_Wl[128][CIN];                     // W lo

// ---------- packed f32x2 helpers ----------
__device__ __forceinline__ unsigned long long pack2(float lo, float hi) {
    unsigned long long r;
    asm("mov.b64 %0, {%1, %2};" : "=l"(r) : "f"(lo), "f"(hi));
    return r;
}
__device__ __forceinline__ void fma2(unsigned long long& d, unsigned long long a,
                                     unsigned long long b) {
    asm("fma.rn.f32x2 %0, %1, %2, %0;" : "+l"(d) : "l"(a), "l"(b));
}
__device__ __forceinline__ float2 unpack2(unsigned long long v) {
    float2 f;
    asm("mov.b64 {%0, %1}, %2;" : "=f"(f.x), "=f"(f.y) : "l"(v));
    return f;
}
__device__ __forceinline__ void split_hl(float v, __half& hi, __half& lo) {
    hi = __float2half_rn(v);
    lo = __float2half_rn(v - __half2float(hi));
}

// ---------- FFMA 64x64 microkernel (fallback paths only) ----------
__device__ __forceinline__ void mm_tile(const float* __restrict__ As,
                                        const float* __restrict__ Bs,
                                        unsigned long long (&acc)[4][2],
                                        int ty, int tx) {
#pragma unroll
    for (int kk = 0; kk < 16; ++kk) {
        float4 av = *(const float4*)(As + kk * 68 + ty * 4);
        float4 bv = *(const float4*)(Bs + kk * 64 + tx * 4);
        unsigned long long b01 = pack2(bv.x, bv.y);
        unsigned long long b23 = pack2(bv.z, bv.w);
        unsigned long long a;
        a = pack2(av.x, av.x); fma2(acc[0][0], a, b01); fma2(acc[0][1], a, b23);
        a = pack2(av.y, av.y); fma2(acc[1][0], a, b01); fma2(acc[1][1], a, b23);
        a = pack2(av.z, av.z); fma2(acc[2][0], a, b01); fma2(acc[2][1], a, b23);
        a = pack2(av.w, av.w); fma2(acc[3][0], a, b01); fma2(acc[3][1], a, b23);
    }
}

// ---------- prep: A (s=0,2) -> fp16 hi/lo, zero-padded; grid (256, 32) ----------
__global__ __launch_bounds__(256) void prep_A(const float* __restrict__ a0,
                                              const float* __restrict__ a1) {
    int j = blockIdx.x;            // 0..255
    int bz = blockIdx.y;           // b*2+s2
    int b = bz >> 1, s2 = bz & 1;
    int k = threadIdx.x;
    const float* src = (s2 ? a1 : a0) + b * KK2;
    float v = (j < K_DIM && k < K_DIM) ? src[j * K_DIM + k] : 0.f;
    __half hi, lo;
    split_hl(v, hi, lo);
    g_Ah[b][2 * s2][j][k] = hi;
    g_Al[b][2 * s2][j][k] = lo;
}

// ---------- prep: A^T (s2=0,1) fp16 via smem transpose; grid (4, 4, 32) --------
__global__ __launch_bounds__(256) void prep_AT(const float* __restrict__ a0,
                                               const float* __restrict__ a1) {
    __shared__ float s[64][65];
    int kt = blockIdx.x, jt = blockIdx.y, bz = blockIdx.z;
    int b = bz >> 1, s2 = bz & 1;
    const float* src = (s2 ? a1 : a0) + b * KK2;
    int t = threadIdx.x;
    int col = t & 63, row4 = t >> 6;
#pragma unroll
    for (int it = 0; it < 16; ++it) {
        int lj = it * 4 + row4;
        int j = jt * 64 + lj, k = kt * 64 + col;
        s[lj][col] = (j < K_DIM && k < K_DIM) ? src[j * K_DIM + k] : 0.f;
    }
    __syncthreads();
#pragma unroll
    for (int it = 0; it < 16; ++it) {
        int r = it * 4 + row4;          // local k
        g_ATh[b][s2][kt * 64 + r][jt * 64 + col] = __float2half_rn(s[col][r]);
    }
}

// ---------- prep: transpose X to [b][l*64+c][k] fp16; 512 thr, float4 ----------
__global__ __launch_bounds__(512) void prep_X(const float* __restrict__ x) {
    extern __shared__ float s_x[];     // [207][68]
    int c = blockIdx.x, b = blockIdx.y;
    const float* xp = x + (long)b * CKL + (long)c * KL;
    int t = threadIdx.x;
#pragma unroll
    for (int it = 0; it < 7; ++it) {
        int idx = it * 512 + t;
        if (idx < 3312) {
            float4 v = ((const float4*)xp)[idx];
            int k = idx >> 4, l4 = (idx & 15) * 4;
            *(float4*)&s_x[k * 68 + l4] = v;
        }
    }
    __syncthreads();
    int kq = t >> 6, l = t & 63;       // kq 0..7, each handles 32 k
    __align__(16) __half hh[32];
#pragma unroll
    for (int i = 0; i < 32; ++i) {
        int k = kq * 32 + i;
        hh[i] = __float2half_rn((k < K_DIM) ? s_x[k * 68 + l] : 0.f);
    }
    uint4* dh = (uint4*)&g_Xh[b][l * 64 + c][kq * 32];
#pragma unroll
    for (int i = 0; i < 4; ++i) dh[i] = ((uint4*)hh)[i];
}

// ---------- prep: x -> channels [0,64) of g_hh, grid (207, 16) -----------------
__global__ __launch_bounds__(256) void prep_xh(const float* __restrict__ x) {
    __shared__ float sx[64][68];
    int j = blockIdx.x, b = blockIdx.y;
    int t = threadIdx.x;
    const float* xp = x + (long)b * CKL + j * 64;
#pragma unroll
    for (int it = 0; it < 4; ++it) {
        int idx = it * 256 + t;        // float4 index within [c][l]
        int c = idx >> 4, l4 = (idx & 15) * 4;
        float4 v = *(const float4*)(xp + (long)c * KL + l4);
        *(float4*)&sx[c][l4] = v;
    }
    __syncthreads();
#pragma unroll
    for (int it = 0; it < 2; ++it) {
        int idx = it * 256 + t;
        int l = idx >> 3, q = idx & 7;       // 8 channels per thread
        __align__(16) __half hh[8];
#pragma unroll
        for (int i = 0; i < 8; ++i) hh[i] = __float2half_rn(sx[q * 8 + i][l]);
        *((uint4*)&g_hh[b][j * 64 + l][0] + q) = *(uint4*)hh;
    }
}

// ---------- prep: W -> padded fp16 hi/lo, grid (160) ----------
__global__ __launch_bounds__(256) void prep_W(const float* __restrict__ W) {
    int idx = blockIdx.x * 256 + threadIdx.x;   // 0..40959
    int o = idx / CIN, i = idx - o * CIN;
    float v = (o < 64) ? W[o * CIN + i] : 0.f;
    __half hi, lo;
    split_hl(v, hi, lo);
    g_Wh[o][i] = hi;
    g_Wl[o][i] = lo;
}

// ---------------- tcgen05 plumbing (expanded only on 'a'-arch pass) ------------
__device__ __forceinline__ uint32_t smem_u32(const void* p) {
    uint32_t a;
    asm("{ .reg .u64 t; cvta.to.shared.u64 t, %1; cvt.u32.u64 %0, t; }" : "=r"(a) : "l"(p));
    return a;
}
#if HAVE_TC
__device__ __forceinline__ uint32_t elect1() {
    uint32_t p;
    asm volatile("{\n\t.reg .pred p;\n\telect.sync _|p, 0xFFFFFFFF;\n\tselp.b32 %0, 1, 0, p;\n\t}"
                 : "=r"(p));
    return p;
}
static constexpr uint64_t DESC_SW128 =
    (uint64_t(2) << 61) | (uint64_t(1) << 46) | (uint64_t(64) << 32) | (uint64_t(1) << 16);
__device__ __forceinline__ uint64_t mk_desc(uint32_t a) {
    return DESC_SW128 | ((uint64_t)(a >> 4) & 0x3FFF);
}
#define MBAR_INIT(a, c) asm volatile("mbarrier.init.shared.b64 [%0], %1;" :: "r"(a), "r"(c) : "memory")
#define MBAR_INVAL(a)   asm volatile("mbarrier.inval.shared.b64 [%0];" :: "r"(a) : "memory")
#define MBAR_WAIT(a, par) do {                                                     \
    uint32_t _m = (a), _p = (par), _d;                                             \
    asm volatile("{\n\t.reg .pred p;\n\t"                                          \
        "mbarrier.try_wait.parity.acquire.cta.shared::cta.b64 p, [%1], %2;\n\t"    \
        "selp.b32 %0, 1, 0, p;\n\t}" : "=r"(_d) : "r"(_m), "r"(_p) : "memory");    \
    if (!_d) {                                                                     \
        asm volatile("{\n\t.reg .pred P1;\n\t"                                     \
            "WL_%=:\n\t"                                                           \
            "mbarrier.try_wait.parity.acquire.cta.shared::cta.b64 P1, [%0], %1, 0x989680;\n\t" \
            "@P1 bra.uni WD_%=;\n\tbra.uni WL_%=;\n\tWD_%=:\n\t}"                  \
            :: "r"(_m), "r"(_p) : "memory");                                       \
    }                                                                              \
} while (0)
#define TC_ALLOC(sm, n) \
    asm volatile("tcgen05.alloc.cta_group::1.sync.aligned.shared::cta.b32 [%0], %1;" :: "r"(sm), "r"(n) : "memory")
#define TC_DEALLOC(t, n) \
    asm volatile("tcgen05.dealloc.cta_group::1.sync.aligned.b32 %0, %1;" :: "r"(t), "r"(n))
#define TC_COMMIT(mb) \
    asm volatile("tcgen05.commit.cta_group::1.mbarrier::arrive::one.shared::cluster.b64 [%0];" :: "r"(mb) : "memory")
#define TC_WAIT_LD()     asm volatile("tcgen05.wait::ld.sync.aligned;" ::: "memory")
#define TC_FENCE_AFTER() asm volatile("tcgen05.fence::after_thread_sync;" ::: "memory")

#define TC_LD_X32(r, ta)                                                            \
    asm volatile("tcgen05.ld.sync.aligned.32x32b.x32.b32 "                          \
        "{%0, %1, %2, %3, %4, %5, %6, %7, %8, %9, %10, %11, %12, %13, %14, %15, "   \
        " %16, %17, %18, %19, %20, %21, %22, %23, %24, %25, %26, %27, %28, %29, %30, %31}, [%32];" \
        : "=r"((r)[0]), "=r"((r)[1]), "=r"((r)[2]), "=r"((r)[3]),                   \
          "=r"((r)[4]), "=r"((r)[5]), "=r"((r)[6]), "=r"((r)[7]),                   \
          "=r"((r)[8]), "=r"((r)[9]), "=r"((r)[10]), "=r"((r)[11]),                 \
          "=r"((r)[12]), "=r"((r)[13]), "=r"((r)[14]), "=r"((r)[15]),               \
          "=r"((r)[16]), "=r"((r)[17]), "=r"((r)[18]), "=r"((r)[19]),               \
          "=r"((r)[20]), "=r"((r)[21]), "=r"((r)[22]), "=r"((r)[23]),               \
          "=r"((r)[24]), "=r"((r)[25]), "=r"((r)[26]), "=r"((r)[27]),               \
          "=r"((r)[28]), "=r"((r)[29]), "=r"((r)[30]), "=r"((r)[31])                \
        : "r"(ta))

// f16 SS MMA, cg1, M=128, N=64 (field layout verified vs bf16 0x8080490)
#define IDESC_F16 0x8100010u
__device__ __forceinline__ void mma16(uint32_t d, uint64_t ad, uint64_t bd, uint32_t en) {
    asm volatile("{\n\t.reg .pred p;\n\tsetp.ne.u32 p, %3, 0;\n\t"
        "tcgen05.mma.cta_group::1.kind::f16 [%0], %1, %2, %4, {%5, %5, %5, %5}, p;\n\t}"
        :: "r"(d), "l"(ad), "l"(bd), "r"(en), "r"(IDESC_F16), "r"(0u) : "memory");
}

// async-copy R rows x 128B from global into SW128 smem tile
template <int R>
__device__ __forceinline__ void ld_tile(uint32_t dst, const __half* src, int stride_h) {
    const char* s8 = (const char*)src;
    long sb = (long)stride_h * 2;
#pragma unroll
    for (int u = 0; u < (R * 8) / 256; ++u) {
        int idx = u * 256 + threadIdx.x;
        int r = idx >> 3, q = idx & 7;
        const void* sp = s8 + (long)r * sb + q * 16;
        uint32_t off = r * 128 + q * 16;
        uint32_t d = dst + (off ^ ((off >> 3) & 0x70));
        asm volatile("cp.async.cg.shared.global [%0], [%1], 16;" :: "r"(d), "l"(sp));
    }
}

__device__ __forceinline__ void load_chunk(uint32_t sb, int ck,
                                           const __half* Ah, const __half* Al, int astr,
                                           const __half* Bh, int bstr) {
    ld_tile<128>(sb,         Ah + ck * 64, astr);
    ld_tile<128>(sb + 16384, Al + ck * 64, astr);
    ld_tile<256>(sb + 32768, Bh + ck * 64, bstr);
    asm volatile("cp.async.commit_group;" ::: "memory");
}

// double-buffered 2-term mainloop; D = 128x256 fp32 in TMEM cols [0,256)
template <int NC>
__device__ __forceinline__ void gemm_main(uint32_t dynb, uint32_t mb, uint32_t tmem,
                                          const __half* Ah, const __half* Al, int astr,
                                          const __half* Bh, int bstr) {
    load_chunk(dynb, 0, Ah, Al, astr, Bh, bstr);
    int p0 = 0, p1 = 0;
#pragma unroll 1
    for (int i = 0; i < NC; ++i) {
        int q = i & 1;
        asm volatile("cp.async.wait_group 0;" ::: "memory");
        asm volatile("fence.proxy.async.shared::cta;" ::: "memory");
        __syncthreads();
        if (threadIdx.x < 32 && elect1()) {
            uint32_t sb = dynb + q * STG;
            uint64_t dAh = mk_desc(sb), dAl = mk_desc(sb + 16384);
            uint64_t dB = mk_desc(sb + 32768);
#pragma unroll
            for (int t = 0; t < 2; ++t) {          // Ah*B, Al*B
                uint64_t ad = t ? dAl : dAh;
#pragma unroll
                for (int ks = 0; ks < 4; ++ks)
#pragma unroll
                    for (int ng = 0; ng < 4; ++ng) {
                        uint32_t en = !(i == 0 && t == 0 && ks == 0);
                        mma16(tmem + ng * 64, ad + ks * 2, dB + ng * 512 + ks * 2, en);
                    }
            }
            TC_COMMIT(mb + q * 8);
        }
        if (i + 1 < NC) {
            int q2 = (i + 1) & 1;
            if (i >= 1) {
                if (q2 == 0) { MBAR_WAIT(mb, p0); p0 ^= 1; }
                else         { MBAR_WAIT(mb + 8, p1); p1 ^= 1; }
            }
            load_chunk(dynb + q2 * STG, i + 1, Ah, Al, astr, Bh, bstr);
        }
    }
    MBAR_WAIT(mb, p0);
    MBAR_WAIT(mb + 8, p1);
    TC_FENCE_AFTER();
}
#endif  // HAVE_TC

// ---------- kernel: A^2 on tensor cores; grid (1, mt=2, b*2+s2=32) -------------
__global__ __launch_bounds__(256, 1) void k_sq() {
    int mt = blockIdx.y, bz = blockIdx.z;
    int b = bz >> 1, s2 = bz & 1;
#if HAVE_TC
    extern __shared__ char dyn[];
    __shared__ uint32_t s_ctrl[1];
    __shared__ __align__(8) unsigned long long s_mb[2];

    uint32_t ctrl = smem_u32(s_ctrl), mb = smem_u32(s_mb);
    if (threadIdx.x < 32) TC_ALLOC(ctrl, 256);
    if (threadIdx.x == 0) { MBAR_INIT(mb, 1); MBAR_INIT(mb + 8, 1); }
    __syncthreads();
    uint32_t tmem;
    asm volatile("ld.shared.b32 %0, [%1];" : "=r"(tmem) : "r"(ctrl));
    uint32_t dynb = (smem_u32(dyn) + 1023u) & ~1023u;

    gemm_main<4>(dynb, mb, tmem,
                 &g_Ah[b][2 * s2][mt * 128][0], &g_Al[b][2 * s2][mt * 128][0], KP,
                 &g_ATh[b][s2][0][0], KP);

    int wid = threadIdx.x >> 5, lane = threadIdx.x & 31;
    if (wid < 4) {
        int j = mt * 128 + wid * 32 + lane;
#pragma unroll 1
        for (int q = 0; q < 8; ++q) {
            __align__(16) uint32_t r[32];
            TC_LD_X32(r, tmem + q * 32);
            TC_WAIT_LD();
            __align__(16) __half hh[32], hl[32];
#pragma unroll
            for (int i = 0; i < 32; ++i) split_hl(__uint_as_float(r[i]), hh[i], hl[i]);
            uint4* dh = (uint4*)&g_Ah[b][2 * s2 + 1][j][q * 32];
            uint4* dl = (uint4*)&g_Al[b][2 * s2 + 1][j][q * 32];
#pragma unroll
            for (int u = 0; u < 4; ++u) { dh[u] = ((uint4*)hh)[u]; dl[u] = ((uint4*)hl)[u]; }
        }
    }
    __syncthreads();
    if (threadIdx.x == 0) { MBAR_INVAL(mb); MBAR_INVAL(mb + 8); }
    if (threadIdx.x < 32) TC_DEALLOC(tmem, 256);
#else
    // FFMA fallback: A^2 tile rows [mt*128,+128) x cols [0,256)
    __shared__ float As[16 * 68];
    __shared__ float Bs[16 * 64];
    int t = threadIdx.x;
    int tx = t & 15, ty = t >> 4;
    int la_k = t & 15, la_j = t >> 4;
    int lb_l = t & 63, lb_k = t >> 6;

    for (int jt = 0; jt < 2; ++jt) {
        int row0 = mt * 128 + jt * 64;
        for (int ct = 0; ct < 4; ++ct) {
            int col0 = ct * 64;
            unsigned long long zz = pack2(0.f, 0.f);
            unsigned long long acc[4][2];
#pragma unroll
            for (int u = 0; u < 4; ++u) { acc[u][0] = zz; acc[u][1] = zz; }
            for (int k0 = 0; k0 < KP; k0 += 16) {
                __syncthreads();
#pragma unroll
                for (int p = 0; p < 4; ++p) {
                    int jj = la_j + p * 16;
                    As[la_k * 68 + jj] =
                        __half2float(g_Ah[b][2 * s2][row0 + jj][k0 + la_k]) +
                        __half2float(g_Al[b][2 * s2][row0 + jj][k0 + la_k]);
                }
#pragma unroll
                for (int p = 0; p < 4; ++p) {
                    int kk = lb_k + p * 4;
                    Bs[kk * 64 + lb_l] =
                        __half2float(g_ATh[b][s2][k0 + kk][col0 + lb_l]);
                }
                __syncthreads();
                mm_tile(As, Bs, acc, ty, tx);
            }
#pragma unroll
            for (int u = 0; u < 4; ++u) {
                int gj = row0 + ty * 4 + u;
                float2 p01 = unpack2(acc[u][0]);
                float2 p23 = unpack2(acc[u][1]);
                float vals[4] = {p01.x, p01.y, p23.x, p23.y};
#pragma unroll
                for (int v = 0; v < 4; ++v) {
                    __half hi, lo;
                    split_hl(vals[v], hi, lo);
                    g_Ah[b][2 * s2 + 1][gj][col0 + tx * 4 + v] = hi;
                    g_Al[b][2 * s2 + 1][gj][col0 + tx * 4 + v] = lo;
                }
            }
            __syncthreads();
        }
    }
#endif
}

// ---------- kernel: diffusion, grid (smt=8, nt=16, b=16) -----------------------
// blockIdx.x = s*2+mt so the 8 CTAs sharing one B tile are launch-adjacent (L2 reuse)
__global__ __launch_bounds__(256, 1) void k_diffuse(const float* __restrict__ x) {
    int smt = blockIdx.x, nt = blockIdx.y, b = blockIdx.z;
    int s = smt >> 1, mt = smt & 1;
#if HAVE_TC
    extern __shared__ char dyn[];
    __shared__ uint32_t s_ctrl[1];
    __shared__ __align__(8) unsigned long long s_mb[2];

    uint32_t ctrl = smem_u32(s_ctrl), mb = smem_u32(s_mb);
    if (threadIdx.x < 32) TC_ALLOC(ctrl, 256);
    if (threadIdx.x == 0) { MBAR_INIT(mb, 1); MBAR_INIT(mb + 8, 1); }
    __syncthreads();
    uint32_t tmem;
    asm volatile("ld.shared.b32 %0, [%1];" : "=r"(tmem) : "r"(ctrl));
    uint32_t dynb = (smem_u32(dyn) + 1023u) & ~1023u;

    gemm_main<4>(dynb, mb, tmem,
                 &g_Ah[b][s][mt * 128][0], &g_Al[b][s][mt * 128][0], KP,
                 &g_Xh[b][nt * 256][0], KP);

    int wid = threadIdx.x >> 5, lane = threadIdx.x & 31;
    if (wid < 4) {  // warps 0-3 cover the 128 TMEM lanes (rows j)
        int j = mt * 128 + wid * 32 + lane;
        bool ok = (j < K_DIM);
        int ch0 = 64 + s * 64;
#pragma unroll 1
        for (int q = 0; q < 8; ++q) {
            __align__(16) uint32_t r[32];
            TC_LD_X32(r, tmem + q * 32);
            TC_WAIT_LD();
            if (ok) {
                int l = nt * 4 + (q >> 1), c0 = (q & 1) * 32;
                __align__(16) __half hh[32];
#pragma unroll
                for (int i = 0; i < 32; ++i)
                    hh[i] = __float2half_rn(__uint_as_float(r[i]));
                uint4* dh = (uint4*)&g_hh[b][j * 64 + l][ch0 + c0];
#pragma unroll
                for (int u = 0; u < 4; ++u) dh[u] = ((uint4*)hh)[u];
            }
        }
    }
    __syncthreads();
    if (threadIdx.x == 0) { MBAR_INVAL(mb); MBAR_INVAL(mb + 8); }
    if (threadIdx.x < 32) TC_DEALLOC(tmem, 256);
#else
    // FFMA fallback (never runs on GB300; correctness-preserving)
    __shared__ float As[16 * 68];
    __shared__ float Bs[16 * 64];
    int t = threadIdx.x;
    int tx = t & 15, ty = t >> 4;
    int la_k = t & 15, la_j = t >> 4;
    int lb_l = t & 63, lb_k = t >> 6;
    int ch0 = 64 + s * 64;

    for (int jt = 0; jt < 2; ++jt) {
        int row0 = mt * 128 + jt * 64;
        if (row0 >= K_DIM) break;
        for (int ct = 0; ct < 4; ++ct) {
            int c = nt * 4 + ct;
            const float* X = x + (long)b * CKL + (long)c * KL;
            unsigned long long zz = pack2(0.f, 0.f);
            unsigned long long acc[4][2];
#pragma unroll
            for (int u = 0; u < 4; ++u) { acc[u][0] = zz; acc[u][1] = zz; }
            for (int k0 = 0; k0 < K_DIM; k0 += 16) {
                __syncthreads();
#pragma unroll
                for (int p = 0; p < 4; ++p) {
                    int jj = la_j + p * 16;
                    int gj = row0 + jj, gk = k0 + la_k;
                    As[la_k * 68 + jj] =
                        (gj < KP && gk < KP)
                            ? (__half2float(g_Ah[b][s][gj][gk]) +
                               __half2float(g_Al[b][s][gj][gk]))
                            : 0.f;
                }
#pragma unroll
                for (int p = 0; p < 4; ++p) {
                    int kk = lb_k + p * 4;
                    int gk = k0 + kk;
                    Bs[kk * 64 + lb_l] = (gk < K_DIM) ? X[gk * 64 + lb_l] : 0.f;
                }
                __syncthreads();
                mm_tile(As, Bs, acc, ty, tx);
            }
#pragma unroll
            for (int u = 0; u < 4; ++u) {
                int gj = row0 + ty * 4 + u;
                if (gj < K_DIM) {
                    float2 p01 = unpack2(acc[u][0]);
                    float2 p23 = unpack2(acc[u][1]);
                    float vals[4] = {p01.x, p01.y, p23.x, p23.y};
#pragma unroll
                    for (int v = 0; v < 4; ++v) {
                        int l = tx * 4 + v;
                        g_hh[b][gj * 64 + l][ch0 + c] = __float2half_rn(vals[v]);
                    }
                }
            }
            __syncthreads();
        }
    }
#endif
}

// ---------- kernel: conv y = W @ h + bias, grid (nt=52, b=16) ------------------
__global__ __launch_bounds__(256, 1) void k_conv(const float* __restrict__ W,
                                                 const float* __restrict__ bias,
                                                 float* __restrict__ y) {
    int nt = blockIdx.x, b = blockIdx.y;
#if HAVE_TC
    extern __shared__ char dyn[];
    __shared__ uint32_t s_ctrl[1];
    __shared__ __align__(8) unsigned long long s_mb[2];

    uint32_t ctrl = smem_u32(s_ctrl), mb = smem_u32(s_mb);
    if (threadIdx.x < 32) TC_ALLOC(ctrl, 256);
    if (threadIdx.x == 0) { MBAR_INIT(mb, 1); MBAR_INIT(mb + 8, 1); }
    __syncthreads();
    uint32_t tmem;
    asm volatile("ld.shared.b32 %0, [%1];" : "=r"(tmem) : "r"(ctrl));
    uint32_t dynb = (smem_u32(dyn) + 1023u) & ~1023u;

    gemm_main<5>(dynb, mb, tmem,
                 &g_Wh[0][0], &g_Wl[0][0], CIN,
                 &g_hh[b][nt * 256][0], CIN);

    int wid = threadIdx.x >> 5, lane = threadIdx.x & 31;
    if (wid < 2) {  // TMEM lanes 0..63 = output channels
        int o = wid * 32 + lane;
        float bv = bias[o];
        float* yp = y + (long)b * CKL + (long)o * KL;
#pragma unroll 1
        for (int q = 0; q < 8; ++q) {
            __align__(16) uint32_t r[32];
            TC_LD_X32(r, tmem + q * 32);
            TC_WAIT_LD();
            int n0 = nt * 256 + q * 32;
            if (n0 < KL) {
                __align__(16) float v[32];
#pragma unroll
                for (int i = 0; i < 32; ++i) v[i] = __uint_as_float(r[i]) + bv;
                uint4* dst = (uint4*)(yp + n0);
#pragma unroll
                for (int u = 0; u < 8; ++u) dst[u] = ((uint4*)v)[u];
            }
        }
    }
    __syncthreads();
    if (threadIdx.x == 0) { MBAR_INVAL(mb); MBAR_INVAL(mb + 8); }
    if (threadIdx.x < 32) TC_DEALLOC(tmem, 256);
#else
    // FFMA fallback
    __shared__ float As[16 * 68];
    __shared__ float Bs[16 * 64];
    int t = threadIdx.x;
    int tx = t & 15, ty = t >> 4;
    int la_k = t & 15, la_j = t >> 4;
    int lb_l = t & 63, lb_k = t >> 6;

    for (int sub = 0; sub < 4; ++sub) {
        int n0 = nt * 256 + sub * 64;
        if (n0 >= KL) break;
        unsigned long long acc[4][2];
#pragma unroll
        for (int u = 0; u < 4; ++u) {
            float bv = bias[ty * 4 + u];
            acc[u][0] = pack2(bv, bv);
            acc[u][1] = pack2(bv, bv);
        }
        for (int i0 = 0; i0 < CIN; i0 += 16) {
            __syncthreads();
#pragma unroll
            for (int p = 0; p < 4; ++p) {
                int o = la_j + p * 16;
                As[la_k * 68 + o] = (o < 64) ? W[o * CIN + i0 + la_k] : 0.f;
            }
#pragma unroll
            for (int p = 0; p < 4; ++p) {
                int ii = lb_k + p * 4;
                int i = i0 + ii;
                int n = n0 + lb_l;
                Bs[ii * 64 + lb_l] = __half2float(g_hh[b][n][i]);
            }
            __syncthreads();
            mm_tile(As, Bs, acc, ty, tx);
        }
#pragma unroll
        for (int u = 0; u < 4; ++u) {
            int o = ty * 4 + u;
            if (o < 64) {
                float2 p01 = unpack2(acc[u][0]);
                float2 p23 = unpack2(acc[u][1]);
                float4 ov = make_float4(p01.x, p01.y, p23.x, p23.y);
                *(float4*)(y + (long)b * CKL + (long)o * KL + n0 + tx * 4) = ov;
            }
        }
        __syncthreads();
    }
#endif
}

extern "C" void kernel_launch(void* const* d_in, const int* in_sizes, int n_in,
                              void* d_out, int out_size) {
    const float* x    = (const float*)d_in[0];   // (16, 64, 13248)
    const float* a0   = (const float*)d_in[1];   // (16, 207, 207)
    const float* a1   = (const float*)d_in[2];   // (16, 207, 207)
    const float* W    = (const float*)d_in[3];   // (64, 320)
    const float* bias = (const float*)d_in[4];   // (64,)
    float* y = (float*)d_out;                    // (16, 64, 13248)

    cudaFuncSetAttribute(k_sq, cudaFuncAttributeMaxDynamicSharedMemorySize,
                         2 * STG + 1024);
    cudaFuncSetAttribute(k_diffuse, cudaFuncAttributeMaxDynamicSharedMemorySize,
                         2 * STG + 1024);
    cudaFuncSetAttribute(k_conv, cudaFuncAttributeMaxDynamicSharedMemorySize,
                         2 * STG + 1024);
    cudaFuncSetAttribute(prep_X, cudaFuncAttributeMaxDynamicSharedMemorySize,
                         207 * 68 * 4);

    dim3 blk(256);
    prep_A<<<dim3(256, 32), blk>>>(a0, a1);
    prep_AT<<<dim3(4, 4, 32), blk>>>(a0, a1);
    k_sq<<<dim3(1, 2, 32), blk, 2 * STG + 1024>>>();
    prep_X<<<dim3(64, 16), dim3(512), 207 * 68 * 4>>>(x);
    prep_xh<<<dim3(207, 16), blk>>>(x);
    prep_W<<<dim3(160), blk>>>(W);
    k_diffuse<<<dim3(8, 16, 16), blk, 2 * STG + 1024>>>(x);
    k_conv<<<dim3(52, 16), blk, 2 * STG + 1024>>>(W, bias, y);
}

// round 14
// speedup vs baseline: 1.6917x; 1.1532x over previous
#include <cuda_runtime.h>
#include <cuda_fp16.h>
#include <cstdint>

#define B_DIM 16
#define C_DIM 64
#define K_DIM 207
#define L_DIM 64
#define KL 13248          // K_DIM * L_DIM
#define CKL (C_DIM * KL)  // 847872
#define KK2 42849         // K_DIM * K_DIM
#define CLDIM 4096        // C_DIM * L_DIM
#define KP 256            // padded K / M for tensor path
#define CIN 320           // conv input channels
#define NH 13312          // padded (j,l) rows = 52*256

// stage layout: A 16K | B 32K = 48KB  (host + device both need this)
#define STG 49152

// Does this device-compilation pass support tcgen05? ('a'-arch targets only)
#if defined(__CUDA_ARCH_FEAT_SM103_ALL) || defined(__CUDA_ARCH_FEAT_SM100_ALL) || \
    defined(__CUDA_ARCH_FEAT_SM101_ALL)
#define HAVE_TC 1
#else
#define HAVE_TC 0
#endif

// Scratch (device globals: allocation-free per harness rules; zero-initialized)
// All GEMM operands single fp16; calibrated error model: ~1.4e-4 RMS per
// quantization, 6 sites stacked in quadrature => ~3.5e-4 total (gate 1e-3).
__device__ __half g_Ah[B_DIM][4][KP][KP];             // A fp16; s:0=A0,1=A0^2,2=A1,3=A1^2
__device__ __half g_ATh[B_DIM][2][KP][KP];            // A^T fp16 (B operand of squaring)
__device__ __half g_Xh[B_DIM][CLDIM][KP];             // X^T fp16: [b][l*64+c][k]
__device__ __half g_hh[B_DIM][NH][CIN];               // h=[x;G] fp16: [b][j*64+l][ch]
__device__ __half g_Wh[128][CIN];                     // W fp16, rows 64..127 zero

// ---------- packed f32x2 helpers ----------
__device__ __forceinline__ unsigned long long pack2(float lo, float hi) {
    unsigned long long r;
    asm("mov.b64 %0, {%1, %2};" : "=l"(r) : "f"(lo), "f"(hi));
    return r;
}
__device__ __forceinline__ void fma2(unsigned long long& d, unsigned long long a,
                                     unsigned long long b) {
    asm("fma.rn.f32x2 %0, %1, %2, %0;" : "+l"(d) : "l"(a), "l"(b));
}
__device__ __forceinline__ float2 unpack2(unsigned long long v) {
    float2 f;
    asm("mov.b64 {%0, %1}, %2;" : "=f"(f.x), "=f"(f.y) : "l"(v));
    return f;
}

// ---------- FFMA 64x64 microkernel (fallback paths only) ----------
__device__ __forceinline__ void mm_tile(const float* __restrict__ As,
                                        const float* __restrict__ Bs,
                                        unsigned long long (&acc)[4][2],
                                        int ty, int tx) {
#pragma unroll
    for (int kk = 0; kk < 16; ++kk) {
        float4 av = *(const float4*)(As + kk * 68 + ty * 4);
        float4 bv = *(const float4*)(Bs + kk * 64 + tx * 4);
        unsigned long long b01 = pack2(bv.x, bv.y);
        unsigned long long b23 = pack2(bv.z, bv.w);
        unsigned long long a;
        a = pack2(av.x, av.x); fma2(acc[0][0], a, b01); fma2(acc[0][1], a, b23);
        a = pack2(av.y, av.y); fma2(acc[1][0], a, b01); fma2(acc[1][1], a, b23);
        a = pack2(av.z, av.z); fma2(acc[2][0], a, b01); fma2(acc[2][1], a, b23);
        a = pack2(av.w, av.w); fma2(acc[3][0], a, b01); fma2(acc[3][1], a, b23);
    }
}

// ---------- prep: A (s=0,2) -> fp16, zero-padded; grid (256, 32) ----------
__global__ __launch_bounds__(256) void prep_A(const float* __restrict__ a0,
                                              const float* __restrict__ a1) {
    int j = blockIdx.x;            // 0..255
    int bz = blockIdx.y;           // b*2+s2
    int b = bz >> 1, s2 = bz & 1;
    int k = threadIdx.x;
    const float* src = (s2 ? a1 : a0) + b * KK2;
    float v = (j < K_DIM && k < K_DIM) ? src[j * K_DIM + k] : 0.f;
    g_Ah[b][2 * s2][j][k] = __float2half_rn(v);
}

// ---------- prep: A^T (s2=0,1) fp16 via smem transpose; grid (4, 4, 32) --------
__global__ __launch_bounds__(256) void prep_AT(const float* __restrict__ a0,
                                               const float* __restrict__ a1) {
    __shared__ float s[64][65];
    int kt = blockIdx.x, jt = blockIdx.y, bz = blockIdx.z;
    int b = bz >> 1, s2 = bz & 1;
    const float* src = (s2 ? a1 : a0) + b * KK2;
    int t = threadIdx.x;
    int col = t & 63, row4 = t >> 6;
#pragma unroll
    for (int it = 0; it < 16; ++it) {
        int lj = it * 4 + row4;
        int j = jt * 64 + lj, k = kt * 64 + col;
        s[lj][col] = (j < K_DIM && k < K_DIM) ? src[j * K_DIM + k] : 0.f;
    }
    __syncthreads();
#pragma unroll
    for (int it = 0; it < 16; ++it) {
        int r = it * 4 + row4;          // local k
        g_ATh[b][s2][kt * 64 + r][jt * 64 + col] = __float2half_rn(s[col][r]);
    }
}

// ---------- prep: transpose X to [b][l*64+c][k] fp16; 512 thr, float4 ----------
__global__ __launch_bounds__(512) void prep_X(const float* __restrict__ x) {
    extern __shared__ float s_x[];     // [207][68]
    int c = blockIdx.x, b = blockIdx.y;
    const float* xp = x + (long)b * CKL + (long)c * KL;
    int t = threadIdx.x;
#pragma unroll
    for (int it = 0; it < 7; ++it) {
        int idx = it * 512 + t;
        if (idx < 3312) {
            float4 v = ((const float4*)xp)[idx];
            int k = idx >> 4, l4 = (idx & 15) * 4;
            *(float4*)&s_x[k * 68 + l4] = v;
        }
    }
    __syncthreads();
    int kq = t >> 6, l = t & 63;       // kq 0..7, each handles 32 k
    __align__(16) __half hh[32];
#pragma unroll
    for (int i = 0; i < 32; ++i) {
        int k = kq * 32 + i;
        hh[i] = __float2half_rn((k < K_DIM) ? s_x[k * 68 + l] : 0.f);
    }
    uint4* dh = (uint4*)&g_Xh[b][l * 64 + c][kq * 32];
#pragma unroll
    for (int i = 0; i < 4; ++i) dh[i] = ((uint4*)hh)[i];
}

// ---------- prep: x -> channels [0,64) of g_hh, grid (207, 16) -----------------
__global__ __launch_bounds__(256) void prep_xh(const float* __restrict__ x) {
    __shared__ float sx[64][68];
    int j = blockIdx.x, b = blockIdx.y;
    int t = threadIdx.x;
    const float* xp = x + (long)b * CKL + j * 64;
#pragma unroll
    for (int it = 0; it < 4; ++it) {
        int idx = it * 256 + t;        // float4 index within [c][l]
        int c = idx >> 4, l4 = (idx & 15) * 4;
        float4 v = *(const float4*)(xp + (long)c * KL + l4);
        *(float4*)&sx[c][l4] = v;
    }
    __syncthreads();
#pragma unroll
    for (int it = 0; it < 2; ++it) {
        int idx = it * 256 + t;
        int l = idx >> 3, q = idx & 7;       // 8 channels per thread
        __align__(16) __half hh[8];
#pragma unroll
        for (int i = 0; i < 8; ++i) hh[i] = __float2half_rn(sx[q * 8 + i][l]);
        *((uint4*)&g_hh[b][j * 64 + l][0] + q) = *(uint4*)hh;
    }
}

// ---------- prep: W -> padded fp16, grid (160) ----------
__global__ __launch_bounds__(256) void prep_W(const float* __restrict__ W) {
    int idx = blockIdx.x * 256 + threadIdx.x;   // 0..40959
    int o = idx / CIN, i = idx - o * CIN;
    float v = (o < 64) ? W[o * CIN + i] : 0.f;
    g_Wh[o][i] = __float2half_rn(v);
}

// ---------------- tcgen05 plumbing (expanded only on 'a'-arch pass) ------------
__device__ __forceinline__ uint32_t smem_u32(const void* p) {
    uint32_t a;
    asm("{ .reg .u64 t; cvta.to.shared.u64 t, %1; cvt.u32.u64 %0, t; }" : "=r"(a) : "l"(p));
    return a;
}
#if HAVE_TC
__device__ __forceinline__ uint32_t elect1() {
    uint32_t p;
    asm volatile("{\n\t.reg .pred p;\n\telect.sync _|p, 0xFFFFFFFF;\n\tselp.b32 %0, 1, 0, p;\n\t}"
                 : "=r"(p));
    return p;
}
static constexpr uint64_t DESC_SW128 =
    (uint64_t(2) << 61) | (uint64_t(1) << 46) | (uint64_t(64) << 32) | (uint64_t(1) << 16);
__device__ __forceinline__ uint64_t mk_desc(uint32_t a) {
    return DESC_SW128 | ((uint64_t)(a >> 4) & 0x3FFF);
}
#define MBAR_INIT(a, c) asm volatile("mbarrier.init.shared.b64 [%0], %1;" :: "r"(a), "r"(c) : "memory")
#define MBAR_INVAL(a)   asm volatile("mbarrier.inval.shared.b64 [%0];" :: "r"(a) : "memory")
#define MBAR_WAIT(a, par) do {                                                     \
    uint32_t _m = (a), _p = (par), _d;                                             \
    asm volatile("{\n\t.reg .pred p;\n\t"                                          \
        "mbarrier.try_wait.parity.acquire.cta.shared::cta.b64 p, [%1], %2;\n\t"    \
        "selp.b32 %0, 1, 0, p;\n\t}" : "=r"(_d) : "r"(_m), "r"(_p) : "memory");    \
    if (!_d) {                                                                     \
        asm volatile("{\n\t.reg .pred P1;\n\t"                                     \
            "WL_%=:\n\t"                                                           \
            "mbarrier.try_wait.parity.acquire.cta.shared::cta.b64 P1, [%0], %1, 0x989680;\n\t" \
            "@P1 bra.uni WD_%=;\n\tbra.uni WL_%=;\n\tWD_%=:\n\t}"                  \
            :: "r"(_m), "r"(_p) : "memory");                                       \
    }                                                                              \
} while (0)
#define TC_ALLOC(sm, n) \
    asm volatile("tcgen05.alloc.cta_group::1.sync.aligned.shared::cta.b32 [%0], %1;" :: "r"(sm), "r"(n) : "memory")
#define TC_DEALLOC(t, n) \
    asm volatile("tcgen05.dealloc.cta_group::1.sync.aligned.b32 %0, %1;" :: "r"(t), "r"(n))
#define TC_COMMIT(mb) \
    asm volatile("tcgen05.commit.cta_group::1.mbarrier::arrive::one.shared::cluster.b64 [%0];" :: "r"(mb) : "memory")
#define TC_WAIT_LD()     asm volatile("tcgen05.wait::ld.sync.aligned;" ::: "memory")
#define TC_FENCE_AFTER() asm volatile("tcgen05.fence::after_thread_sync;" ::: "memory")

#define TC_LD_X32(r, ta)                                                            \
    asm volatile("tcgen05.ld.sync.aligned.32x32b.x32.b32 "                          \
        "{%0, %1, %2, %3, %4, %5, %6, %7, %8, %9, %10, %11, %12, %13, %14, %15, "   \
        " %16, %17, %18, %19, %20, %21, %22, %23, %24, %25, %26, %27, %28, %29, %30, %31}, [%32];" \
        : "=r"((r)[0]), "=r"((r)[1]), "=r"((r)[2]), "=r"((r)[3]),                   \
          "=r"((r)[4]), "=r"((r)[5]), "=r"((r)[6]), "=r"((r)[7]),                   \
          "=r"((r)[8]), "=r"((r)[9]), "=r"((r)[10]), "=r"((r)[11]),                 \
          "=r"((r)[12]), "=r"((r)[13]), "=r"((r)[14]), "=r"((r)[15]),               \
          "=r"((r)[16]), "=r"((r)[17]), "=r"((r)[18]), "=r"((r)[19]),               \
          "=r"((r)[20]), "=r"((r)[21]), "=r"((r)[22]), "=r"((r)[23]),               \
          "=r"((r)[24]), "=r"((r)[25]), "=r"((r)[26]), "=r"((r)[27]),               \
          "=r"((r)[28]), "=r"((r)[29]), "=r"((r)[30]), "=r"((r)[31])                \
        : "r"(ta))

// f16 SS MMA, cg1, M=128, N=64 (field layout verified vs bf16 0x8080490)
#define IDESC_F16 0x8100010u
__device__ __forceinline__ void mma16(uint32_t d, uint64_t ad, uint64_t bd, uint32_t en) {
    asm volatile("{\n\t.reg .pred p;\n\tsetp.ne.u32 p, %3, 0;\n\t"
        "tcgen05.mma.cta_group::1.kind::f16 [%0], %1, %2, %4, {%5, %5, %5, %5}, p;\n\t}"
        :: "r"(d), "l"(ad), "l"(bd), "r"(en), "r"(IDESC_F16), "r"(0u) : "memory");
}

// async-copy R rows x 128B from global into SW128 smem tile
template <int R>
__device__ __forceinline__ void ld_tile(uint32_t dst, const __half* src, int stride_h) {
    const char* s8 = (const char*)src;
    long sb = (long)stride_h * 2;
#pragma unroll
    for (int u = 0; u < (R * 8) / 256; ++u) {
        int idx = u * 256 + threadIdx.x;
        int r = idx >> 3, q = idx & 7;
        const void* sp = s8 + (long)r * sb + q * 16;
        uint32_t off = r * 128 + q * 16;
        uint32_t d = dst + (off ^ ((off >> 3) & 0x70));
        asm volatile("cp.async.cg.shared.global [%0], [%1], 16;" :: "r"(d), "l"(sp));
    }
}

__device__ __forceinline__ void load_chunk(uint32_t sb, int ck,
                                           const __half* A, int astr,
                                           const __half* B, int bstr) {
    ld_tile<128>(sb,         A + ck * 64, astr);
    ld_tile<256>(sb + 16384, B + ck * 64, bstr);
    asm volatile("cp.async.commit_group;" ::: "memory");
}

// double-buffered single-term mainloop; D = 128x256 fp32 in TMEM cols [0,256)
template <int NC>
__device__ __forceinline__ void gemm_main(uint32_t dynb, uint32_t mb, uint32_t tmem,
                                          const __half* A, int astr,
                                          const __half* B, int bstr) {
    load_chunk(dynb, 0, A, astr, B, bstr);
    int p0 = 0, p1 = 0;
#pragma unroll 1
    for (int i = 0; i < NC; ++i) {
        int q = i & 1;
        asm volatile("cp.async.wait_group 0;" ::: "memory");
        asm volatile("fence.proxy.async.shared::cta;" ::: "memory");
        __syncthreads();
        if (threadIdx.x < 32 && elect1()) {
            uint32_t sb = dynb + q * STG;
            uint64_t dA = mk_desc(sb);
            uint64_t dB = mk_desc(sb + 16384);
#pragma unroll
            for (int ks = 0; ks < 4; ++ks)
#pragma unroll
                for (int ng = 0; ng < 4; ++ng) {
                    uint32_t en = !(i == 0 && ks == 0);
                    mma16(tmem + ng * 64, dA + ks * 2, dB + ng * 512 + ks * 2, en);
                }
            TC_COMMIT(mb + q * 8);
        }
        if (i + 1 < NC) {
            int q2 = (i + 1) & 1;
            if (i >= 1) {
                if (q2 == 0) { MBAR_WAIT(mb, p0); p0 ^= 1; }
                else         { MBAR_WAIT(mb + 8, p1); p1 ^= 1; }
            }
            load_chunk(dynb + q2 * STG, i + 1, A, astr, B, bstr);
        }
    }
    MBAR_WAIT(mb, p0);
    MBAR_WAIT(mb + 8, p1);
    TC_FENCE_AFTER();
}
#endif  // HAVE_TC

// ---------- kernel: A^2 on tensor cores; grid (1, mt=2, b*2+s2=32) -------------
__global__ __launch_bounds__(256, 1) void k_sq() {
    int mt = blockIdx.y, bz = blockIdx.z;
    int b = bz >> 1, s2 = bz & 1;
#if HAVE_TC
    extern __shared__ char dyn[];
    __shared__ uint32_t s_ctrl[1];
    __shared__ __align__(8) unsigned long long s_mb[2];

    uint32_t ctrl = smem_u32(s_ctrl), mb = smem_u32(s_mb);
    if (threadIdx.x < 32) TC_ALLOC(ctrl, 256);
    if (threadIdx.x == 0) { MBAR_INIT(mb, 1); MBAR_INIT(mb + 8, 1); }
    __syncthreads();
    uint32_t tmem;
    asm volatile("ld.shared.b32 %0, [%1];" : "=r"(tmem) : "r"(ctrl));
    uint32_t dynb = (smem_u32(dyn) + 1023u) & ~1023u;

    gemm_main<4>(dynb, mb, tmem,
                 &g_Ah[b][2 * s2][mt * 128][0], KP,
                 &g_ATh[b][s2][0][0], KP);

    int wid = threadIdx.x >> 5, lane = threadIdx.x & 31;
    if (wid < 4) {
        int j = mt * 128 + wid * 32 + lane;
#pragma unroll 1
        for (int q = 0; q < 8; ++q) {
            __align__(16) uint32_t r[32];
            TC_LD_X32(r, tmem + q * 32);
            TC_WAIT_LD();
            __align__(16) __half hh[32];
#pragma unroll
            for (int i = 0; i < 32; ++i)
                hh[i] = __float2half_rn(__uint_as_float(r[i]));
            uint4* dh = (uint4*)&g_Ah[b][2 * s2 + 1][j][q * 32];
#pragma unroll
            for (int u = 0; u < 4; ++u) dh[u] = ((uint4*)hh)[u];
        }
    }
    __syncthreads();
    if (threadIdx.x == 0) { MBAR_INVAL(mb); MBAR_INVAL(mb + 8); }
    if (threadIdx.x < 32) TC_DEALLOC(tmem, 256);
#else
    // FFMA fallback: A^2 tile rows [mt*128,+128) x cols [0,256)
    __shared__ float As[16 * 68];
    __shared__ float Bs[16 * 64];
    int t = threadIdx.x;
    int tx = t & 15, ty = t >> 4;
    int la_k = t & 15, la_j = t >> 4;
    int lb_l = t & 63, lb_k = t >> 6;

    for (int jt = 0; jt < 2; ++jt) {
        int row0 = mt * 128 + jt * 64;
        for (int ct = 0; ct < 4; ++ct) {
            int col0 = ct * 64;
            unsigned long long zz = pack2(0.f, 0.f);
            unsigned long long acc[4][2];
#pragma unroll
            for (int u = 0; u < 4; ++u) { acc[u][0] = zz; acc[u][1] = zz; }
            for (int k0 = 0; k0 < KP; k0 += 16) {
                __syncthreads();
#pragma unroll
                for (int p = 0; p < 4; ++p) {
                    int jj = la_j + p * 16;
                    As[la_k * 68 + jj] =
                        __half2float(g_Ah[b][2 * s2][row0 + jj][k0 + la_k]);
                }
#pragma unroll
                for (int p = 0; p < 4; ++p) {
                    int kk = lb_k + p * 4;
                    Bs[kk * 64 + lb_l] =
                        __half2float(g_ATh[b][s2][k0 + kk][col0 + lb_l]);
                }
                __syncthreads();
                mm_tile(As, Bs, acc, ty, tx);
            }
#pragma unroll
            for (int u = 0; u < 4; ++u) {
                int gj = row0 + ty * 4 + u;
                float2 p01 = unpack2(acc[u][0]);
                float2 p23 = unpack2(acc[u][1]);
                float vals[4] = {p01.x, p01.y, p23.x, p23.y};
#pragma unroll
                for (int v = 0; v < 4; ++v)
                    g_Ah[b][2 * s2 + 1][gj][col0 + tx * 4 + v] =
                        __float2half_rn(vals[v]);
            }
            __syncthreads();
        }
    }
#endif
}

// ---------- kernel: diffusion, grid (smt=8, nt=16, b=16) -----------------------
// blockIdx.x = s*2+mt so the 8 CTAs sharing one B tile are launch-adjacent (L2 reuse)
__global__ __launch_bounds__(256, 1) void k_diffuse(const float* __restrict__ x) {
    int smt = blockIdx.x, nt = blockIdx.y, b = blockIdx.z;
    int s = smt >> 1, mt = smt & 1;
#if HAVE_TC
    extern __shared__ char dyn[];
    __shared__ uint32_t s_ctrl[1];
    __shared__ __align__(8) unsigned long long s_mb[2];

    uint32_t ctrl = smem_u32(s_ctrl), mb = smem_u32(s_mb);
    if (threadIdx.x < 32) TC_ALLOC(ctrl, 256);
    if (threadIdx.x == 0) { MBAR_INIT(mb, 1); MBAR_INIT(mb + 8, 1); }
    __syncthreads();
    uint32_t tmem;
    asm volatile("ld.shared.b32 %0, [%1];" : "=r"(tmem) : "r"(ctrl));
    uint32_t dynb = (smem_u32(dyn) + 1023u) & ~1023u;

    gemm_main<4>(dynb, mb, tmem,
                 &g_Ah[b][s][mt * 128][0], KP,
                 &g_Xh[b][nt * 256][0], KP);

    int wid = threadIdx.x >> 5, lane = threadIdx.x & 31;
    if (wid < 4) {  // warps 0-3 cover the 128 TMEM lanes (rows j)
        int j = mt * 128 + wid * 32 + lane;
        bool ok = (j < K_DIM);
        int ch0 = 64 + s * 64;
#pragma unroll 1
        for (int q = 0; q < 8; ++q) {
            __align__(16) uint32_t r[32];
            TC_LD_X32(r, tmem + q * 32);
            TC_WAIT_LD();
            if (ok) {
                int l = nt * 4 + (q >> 1), c0 = (q & 1) * 32;
                __align__(16) __half hh[32];
#pragma unroll
                for (int i = 0; i < 32; ++i)
                    hh[i] = __float2half_rn(__uint_as_float(r[i]));
                uint4* dh = (uint4*)&g_hh[b][j * 64 + l][ch0 + c0];
#pragma unroll
                for (int u = 0; u < 4; ++u) dh[u] = ((uint4*)hh)[u];
            }
        }
    }
    __syncthreads();
    if (threadIdx.x == 0) { MBAR_INVAL(mb); MBAR_INVAL(mb + 8); }
    if (threadIdx.x < 32) TC_DEALLOC(tmem, 256);
#else
    // FFMA fallback (never runs on GB300; correctness-preserving)
    __shared__ float As[16 * 68];
    __shared__ float Bs[16 * 64];
    int t = threadIdx.x;
    int tx = t & 15, ty = t >> 4;
    int la_k = t & 15, la_j = t >> 4;
    int lb_l = t & 63, lb_k = t >> 6;
    int ch0 = 64 + s * 64;

    for (int jt = 0; jt < 2; ++jt) {
        int row0 = mt * 128 + jt * 64;
        if (row0 >= K_DIM) break;
        for (int ct = 0; ct < 4; ++ct) {
            int c = nt * 4 + ct;
            const float* X = x + (long)b * CKL + (long)c * KL;
            unsigned long long zz = pack2(0.f, 0.f);
            unsigned long long acc[4][2];
#pragma unroll
            for (int u = 0; u < 4; ++u) { acc[u][0] = zz; acc[u][1] = zz; }
            for (int k0 = 0; k0 < K_DIM; k0 += 16) {
                __syncthreads();
#pragma unroll
                for (int p = 0; p < 4; ++p) {
                    int jj = la_j + p * 16;
                    int gj = row0 + jj, gk = k0 + la_k;
                    As[la_k * 68 + jj] =
                        (gj < KP && gk < KP)
                            ? __half2float(g_Ah[b][s][gj][gk]) : 0.f;
                }
#pragma unroll
                for (int p = 0; p < 4; ++p) {
                    int kk = lb_k + p * 4;
                    int gk = k0 + kk;
                    Bs[kk * 64 + lb_l] = (gk < K_DIM) ? X[gk * 64 + lb_l] : 0.f;
                }
                __syncthreads();
                mm_tile(As, Bs, acc, ty, tx);
            }
#pragma unroll
            for (int u = 0; u < 4; ++u) {
                int gj = row0 + ty * 4 + u;
                if (gj < K_DIM) {
                    float2 p01 = unpack2(acc[u][0]);
                    float2 p23 = unpack2(acc[u][1]);
                    float vals[4] = {p01.x, p01.y, p23.x, p23.y};
#pragma unroll
                    for (int v = 0; v < 4; ++v) {
                        int l = tx * 4 + v;
                        g_hh[b][gj * 64 + l][ch0 + c] = __float2half_rn(vals[v]);
                    }
                }
            }
            __syncthreads();
        }
    }
#endif
}

// ---------- kernel: conv y = W @ h + bias, grid (nt=52, b=16) ------------------
__global__ __launch_bounds__(256, 1) void k_conv(const float* __restrict__ W,
                                                 const float* __restrict__ bias,
                                                 float* __restrict__ y) {
    int nt = blockIdx.x, b = blockIdx.y;
#if HAVE_TC
    extern __shared__ char dyn[];
    __shared__ uint32_t s_ctrl[1];
    __shared__ __align__(8) unsigned long long s_mb[2];

    uint32_t ctrl = smem_u32(s_ctrl), mb = smem_u32(s_mb);
    if (threadIdx.x < 32) TC_ALLOC(ctrl, 256);
    if (threadIdx.x == 0) { MBAR_INIT(mb, 1); MBAR_INIT(mb + 8, 1); }
    __syncthreads();
    uint32_t tmem;
    asm volatile("ld.shared.b32 %0, [%1];" : "=r"(tmem) : "r"(ctrl));
    uint32_t dynb = (smem_u32(dyn) + 1023u) & ~1023u;

    gemm_main<5>(dynb, mb, tmem,
                 &g_Wh[0][0], CIN,
                 &g_hh[b][nt * 256][0], CIN);

    int wid = threadIdx.x >> 5, lane = threadIdx.x & 31;
    if (wid < 2) {  // TMEM lanes 0..63 = output channels
        int o = wid * 32 + lane;
        float bv = bias[o];
        float* yp = y + (long)b * CKL + (long)o * KL;
#pragma unroll 1
        for (int q = 0; q < 8; ++q) {
            __align__(16) uint32_t r[32];
            TC_LD_X32(r, tmem + q * 32);
            TC_WAIT_LD();
            int n0 = nt * 256 + q * 32;
            if (n0 < KL) {
                __align__(16) float v[32];
#pragma unroll
                for (int i = 0; i < 32; ++i) v[i] = __uint_as_float(r[i]) + bv;
                uint4* dst = (uint4*)(yp + n0);
#pragma unroll
                for (int u = 0; u < 8; ++u) dst[u] = ((uint4*)v)[u];
            }
        }
    }
    __syncthreads();
    if (threadIdx.x == 0) { MBAR_INVAL(mb); MBAR_INVAL(mb + 8); }
    if (threadIdx.x < 32) TC_DEALLOC(tmem, 256);
#else
    // FFMA fallback
    __shared__ float As[16 * 68];
    __shared__ float Bs[16 * 64];
    int t = threadIdx.x;
    int tx = t & 15, ty = t >> 4;
    int la_k = t & 15, la_j = t >> 4;
    int lb_l = t & 63, lb_k = t >> 6;

    for (int sub = 0; sub < 4; ++sub) {
        int n0 = nt * 256 + sub * 64;
        if (n0 >= KL) break;
        unsigned long long acc[4][2];
#pragma unroll
        for (int u = 0; u < 4; ++u) {
            float bv = bias[ty * 4 + u];
            acc[u][0] = pack2(bv, bv);
            acc[u][1] = pack2(bv, bv);
        }
        for (int i0 = 0; i0 < CIN; i0 += 16) {
            __syncthreads();
#pragma unroll
            for (int p = 0; p < 4; ++p) {
                int o = la_j + p * 16;
                As[la_k * 68 + o] = (o < 64) ? W[o * CIN + i0 + la_k] : 0.f;
            }
#pragma unroll
            for (int p = 0; p < 4; ++p) {
                int ii = lb_k + p * 4;
                int i = i0 + ii;
                int n = n0 + lb_l;
                Bs[ii * 64 + lb_l] = __half2float(g_hh[b][n][i]);
            }
            __syncthreads();
            mm_tile(As, Bs, acc, ty, tx);
        }
#pragma unroll
        for (int u = 0; u < 4; ++u) {
            int o = ty * 4 + u;
            if (o < 64) {
                float2 p01 = unpack2(acc[u][0]);
                float2 p23 = unpack2(acc[u][1]);
                float4 ov = make_float4(p01.x, p01.y, p23.x, p23.y);
                *(float4*)(y + (long)b * CKL + (long)o * KL + n0 + tx * 4) = ov;
            }
        }
        __syncthreads();
    }
#endif
}

extern "C" void kernel_launch(void* const* d_in, const int* in_sizes, int n_in,
                              void* d_out, int out_size) {
    const float* x    = (const float*)d_in[0];   // (16, 64, 13248)
    const float* a0   = (const float*)d_in[1];   // (16, 207, 207)
    const float* a1   = (const float*)d_in[2];   // (16, 207, 207)
    const float* W    = (const float*)d_in[3];   // (64, 320)
    const float* bias = (const float*)d_in[4];   // (64,)
    float* y = (float*)d_out;                    // (16, 64, 13248)

    cudaFuncSetAttribute(k_sq, cudaFuncAttributeMaxDynamicSharedMemorySize,
                         2 * STG + 1024);
    cudaFuncSetAttribute(k_diffuse, cudaFuncAttributeMaxDynamicSharedMemorySize,
                         2 * STG + 1024);
    cudaFuncSetAttribute(k_conv, cudaFuncAttributeMaxDynamicSharedMemorySize,
                         2 * STG + 1024);
    cudaFuncSetAttribute(prep_X, cudaFuncAttributeMaxDynamicSharedMemorySize,
                         207 * 68 * 4);

    dim3 blk(256);
    prep_A<<<dim3(256, 32), blk>>>(a0, a1);
    prep_AT<<<dim3(4, 4, 32), blk>>>(a0, a1);
    k_sq<<<dim3(1, 2, 32), blk, 2 * STG + 1024>>>();
    prep_X<<<dim3(64, 16), dim3(512), 207 * 68 * 4>>>(x);
    prep_xh<<<dim3(207, 16), blk>>>(x);
    prep_W<<<dim3(160), blk>>>(W);
    k_diffuse<<<dim3(8, 16, 16), blk, 2 * STG + 1024>>>(x);
    k_conv<<<dim3(52, 16), blk, 2 * STG + 1024>>>(W, bias, y);
}